// round 2
// baseline (speedup 1.0000x reference)
#include <cuda_runtime.h>
#include <cuda_bf16.h>
#include <cstdint>

// Problem constants
#define NQ      8192        // B*S queries
#define CDIM    512         // feature dim (K of the GEMM)
#define MROWS   32768       // memory table rows
#define TOPK    5
#define NCH     8           // M chunks (candidate stage)
#define MCHUNK  (MROWS/NCH) // 4096
#define NCAND   (NCH*TOPK)  // 40

// GEMM tiling
#define QT        128       // queries per block
#define NT        64        // memory rows per inner tile
#define KC        64        // k-chunk for M tile streaming
#define NKC       (CDIM/KC) // 8
#define MT_PER    (MCHUNK/NT) // 64
#define SQ_STRIDE 520       // bf16 elems per sQ row (512 + 8 pad)
#define SM_STRIDE 72        // bf16 elems per sM row (64 + 8 pad)
#define SS_STRIDE 65        // floats per sSim row (64 + 1 pad)

#define SMEM_BYTES (QT*SQ_STRIDE*2 + 2*NT*SM_STRIDE*2 + QT*SS_STRIDE*4) // 184832

// Scratch (device globals: allocation-free)
__device__ __nv_bfloat16 g_qn[(size_t)NQ*CDIM];
__device__ __nv_bfloat16 g_mn[(size_t)MROWS*CDIM];
__device__ float g_minv[MROWS];
__device__ float g_cscore[(size_t)NQ*NCAND];
__device__ int   g_cidx[(size_t)NQ*NCAND];

__device__ __forceinline__ uint32_t smem_u32(const void* p){
    return (uint32_t)__cvta_generic_to_shared(p);
}
__device__ __forceinline__ float warp_sum(float v){
    #pragma unroll
    for (int o=16;o;o>>=1) v += __shfl_xor_sync(0xffffffffu, v, o);
    return v;
}

// ---------------------------------------------------------------------------
// Kernel 1/2: L2-normalize rows (fp32 in -> bf16 out). MODE 0: queries, 1: memory.
// One warp per row; 256 threads = 8 rows/block.
// ---------------------------------------------------------------------------
template<int MODE>
__global__ void normalize_kernel(const float* __restrict__ in){
    const int rows = MODE ? MROWS : NQ;
    __nv_bfloat16* outb = MODE ? g_mn : g_qn;
    int row  = blockIdx.x*8 + (threadIdx.x >> 5);
    int lane = threadIdx.x & 31;
    if (row >= rows) return;
    const float4* src = (const float4*)(in + (size_t)row*CDIM);
    float4 v[4];
    float ss = 0.f;
    #pragma unroll
    for (int w=0; w<4; w++){
        v[w] = src[lane + w*32];
        ss += v[w].x*v[w].x + v[w].y*v[w].y + v[w].z*v[w].z + v[w].w*v[w].w;
    }
    ss = warp_sum(ss);
    float inv = 1.0f / fmaxf(sqrtf(ss), 1e-12f);
    __nv_bfloat16* dst = outb + (size_t)row*CDIM;
    #pragma unroll
    for (int w=0; w<4; w++){
        __nv_bfloat162 p0 = __floats2bfloat162_rn(v[w].x*inv, v[w].y*inv);
        __nv_bfloat162 p1 = __floats2bfloat162_rn(v[w].z*inv, v[w].w*inv);
        uint2 st;
        st.x = *(uint32_t*)&p0;
        st.y = *(uint32_t*)&p1;
        *(uint2*)(dst + (lane + w*32)*4) = st;
    }
    if (MODE && lane==0) g_minv[row] = inv;
}

// ---------------------------------------------------------------------------
// Kernel 3: fused bf16 HMMA GEMM (128q x 4096m per block, K=512) + streaming
// per-chunk top-5. grid = (NCH, NQ/QT). Q tile lives in SMEM for full K.
// ---------------------------------------------------------------------------
__global__ void __launch_bounds__(256,1) sim_topk_kernel(){
    extern __shared__ __align__(16) char smraw[];
    __nv_bfloat16* sQ  = (__nv_bfloat16*)smraw;
    __nv_bfloat16* sM  = (__nv_bfloat16*)(smraw + QT*SQ_STRIDE*2);
    float*         sSim= (float*)(smraw + QT*SQ_STRIDE*2 + 2*NT*SM_STRIDE*2);

    const int tid  = threadIdx.x;
    const int lane = tid & 31;
    const int wid  = tid >> 5;
    const int chunk = blockIdx.x;
    const int qbase = blockIdx.y * QT;
    const int mbase = chunk * MCHUNK;

    // Load Q tile (128 x 512 bf16) into SMEM, padded rows (conflict-free ldmatrix).
    const uint4* gq = (const uint4*)g_qn;   // 8 bf16 per uint4, 64 per row
    #pragma unroll
    for (int i=0; i<(QT*64)/256; i++){
        int idx = tid + i*256;
        int r = idx >> 6, c = idx & 63;
        uint4 val = gq[(size_t)(qbase + r)*64 + c];
        *(uint4*)(sQ + r*SQ_STRIDE + c*8) = val;
    }

    const int wq = (wid & 1) * 64;   // warp's 64-query slab
    const int wn = (wid >> 1) * 16;  // warp's 16-memory-col slab

    // Running top-5 (only threads < 128 use it; kept in registers)
    float s0=-2.f,s1=-2.f,s2=-2.f,s3=-2.f,s4=-2.f;
    int   i0=0,i1=0,i2=0,i3=0,i4=0;

    const uint4* gm = (const uint4*)g_mn;
    const int r0 = tid >> 3,       c0 = tid & 7;  // 512 uint4 per M-tile k-chunk: 2/thread
    const int r1 = (tid+256) >> 3;                // second item, same c

    __syncthreads();

    for (int mt=0; mt<MT_PER; mt++){
        const int mrow0 = mbase + mt*NT;
        float acc[4][2][4];
        #pragma unroll
        for (int a=0;a<4;a++)
            #pragma unroll
            for (int b=0;b<2;b++)
                #pragma unroll
                for (int d=0;d<4;d++) acc[a][b][d]=0.f;

        // Prefetch k-chunk 0 into regs, stage to buffer 0
        uint4 pa = gm[(size_t)(mrow0+r0)*64 + c0];
        uint4 pb = gm[(size_t)(mrow0+r1)*64 + c0];
        *(uint4*)(sM + r0*SM_STRIDE + c0*8) = pa;
        *(uint4*)(sM + r1*SM_STRIDE + c0*8) = pb;
        __syncthreads();

        #pragma unroll
        for (int kc=0; kc<NKC; kc++){
            if (kc+1 < NKC){
                pa = gm[(size_t)(mrow0+r0)*64 + (kc+1)*8 + c0];
                pb = gm[(size_t)(mrow0+r1)*64 + (kc+1)*8 + c0];
            }
            const __nv_bfloat16* mb = sM + (kc & 1)*(NT*SM_STRIDE);
            #pragma unroll
            for (int k16=0; k16<KC/16; k16++){
                // B fragments: memory rows are k-contiguous == col-major B. No .trans.
                uint32_t bfr[2][2];
                #pragma unroll
                for (int nt=0; nt<2; nt++){
                    int brow = wn + nt*8 + (lane & 7);
                    int bk   = k16*16 + ((lane >> 3) & 1)*8;
                    uint32_t ba = smem_u32(mb + brow*SM_STRIDE + bk);
                    asm volatile("ldmatrix.sync.aligned.m8n8.x2.shared.b16 {%0,%1}, [%2];"
                                 : "=r"(bfr[nt][0]), "=r"(bfr[nt][1]) : "r"(ba));
                }
                #pragma unroll
                for (int qt=0; qt<4; qt++){
                    uint32_t a0,a1,a2,a3;
                    int arow = wq + qt*16 + (lane & 15);
                    int ak   = kc*KC + k16*16 + (lane >> 4)*8;
                    uint32_t aa = smem_u32(sQ + arow*SQ_STRIDE + ak);
                    asm volatile("ldmatrix.sync.aligned.m8n8.x4.shared.b16 {%0,%1,%2,%3}, [%4];"
                                 : "=r"(a0),"=r"(a1),"=r"(a2),"=r"(a3) : "r"(aa));
                    #pragma unroll
                    for (int nt=0; nt<2; nt++){
                        asm volatile(
                          "mma.sync.aligned.m16n8k16.row.col.f32.bf16.bf16.f32 "
                          "{%0,%1,%2,%3}, {%4,%5,%6,%7}, {%8,%9}, {%0,%1,%2,%3};"
                          : "+f"(acc[qt][nt][0]),"+f"(acc[qt][nt][1]),
                            "+f"(acc[qt][nt][2]),"+f"(acc[qt][nt][3])
                          : "r"(a0),"r"(a1),"r"(a2),"r"(a3),
                            "r"(bfr[nt][0]),"r"(bfr[nt][1]));
                    }
                }
            }
            if (kc+1 < NKC){
                __nv_bfloat16* db = sM + ((kc+1)&1)*(NT*SM_STRIDE);
                *(uint4*)(db + r0*SM_STRIDE + c0*8) = pa;
                *(uint4*)(db + r1*SM_STRIDE + c0*8) = pb;
            }
            __syncthreads();
        }

        // Spill 128x64 score tile to SMEM (mma D-fragment layout).
        #pragma unroll
        for (int qt=0; qt<4; qt++){
            #pragma unroll
            for (int nt=0; nt<2; nt++){
                int r = wq + qt*16 + (lane >> 2);
                int c = wn + nt*8  + (lane & 3)*2;
                sSim[r*SS_STRIDE + c]         = acc[qt][nt][0];
                sSim[r*SS_STRIDE + c + 1]     = acc[qt][nt][1];
                sSim[(r+8)*SS_STRIDE + c]     = acc[qt][nt][2];
                sSim[(r+8)*SS_STRIDE + c + 1] = acc[qt][nt][3];
            }
        }
        __syncthreads();

        // 128 scan threads update running top-5 (strict >, earlier index wins ties).
        if (tid < QT){
            const float* row = sSim + tid*SS_STRIDE;
            #pragma unroll 4
            for (int c=0; c<NT; c++){
                float v = row[c];
                int id = mrow0 + c;
                if (v > s4){
                    if (v > s2){
                        if (v > s1){
                            if (v > s0){ s4=s3;i4=i3; s3=s2;i3=i2; s2=s1;i2=i1; s1=s0;i1=i0; s0=v;i0=id; }
                            else       { s4=s3;i4=i3; s3=s2;i3=i2; s2=s1;i2=i1; s1=v;i1=id; }
                        } else         { s4=s3;i4=i3; s3=s2;i3=i2; s2=v;i2=id; }
                    } else {
                        if (v > s3)    { s4=s3;i4=i3; s3=v;i3=id; }
                        else           { s4=v;i4=id; }
                    }
                }
            }
        }
        __syncthreads();
    }

    if (tid < QT){
        int q = qbase + tid;
        float* cs = g_cscore + (size_t)q*NCAND + chunk*TOPK;
        int*   ci = g_cidx   + (size_t)q*NCAND + chunk*TOPK;
        cs[0]=s0; cs[1]=s1; cs[2]=s2; cs[3]=s3; cs[4]=s4;
        ci[0]=i0; ci[1]=i1; ci[2]=i2; ci[3]=i3; ci[4]=i4;
    }
}

// ---------------------------------------------------------------------------
// Kernel 4: exact fp32 rescore of 40 candidates, true top-5, softmax, gather,
// out = x + 0.5 * retrieved. One warp per query.
// ---------------------------------------------------------------------------
__global__ void merge_kernel(const float* __restrict__ x,
                             const float* __restrict__ mem,
                             float* __restrict__ out){
    int gw   = (blockIdx.x*blockDim.x + threadIdx.x) >> 5;
    int lane = threadIdx.x & 31;
    if (gw >= NQ) return;

    const float4* xr = (const float4*)(x + (size_t)gw*CDIM);
    float4 xv[4];
    float ss = 0.f;
    #pragma unroll
    for (int w=0; w<4; w++){
        xv[w] = xr[lane + w*32];
        ss += xv[w].x*xv[w].x + xv[w].y*xv[w].y + xv[w].z*xv[w].z + xv[w].w*xv[w].w;
    }
    ss = warp_sum(ss);
    float qinv = 1.0f / fmaxf(sqrtf(ss), 1e-12f);

    float ts[TOPK]; int ti[TOPK];
    #pragma unroll
    for (int r=0;r<TOPK;r++){ ts[r]=-2.f; ti[r]=0; }

    for (int c=0; c<NCAND; c++){
        int idx = g_cidx[(size_t)gw*NCAND + c];
        const float4* mr = (const float4*)(mem + (size_t)idx*CDIM);
        float d = 0.f;
        #pragma unroll
        for (int w=0; w<4; w++){
            float4 mv = mr[lane + w*32];
            d += xv[w].x*mv.x + xv[w].y*mv.y + xv[w].z*mv.z + xv[w].w*mv.w;
        }
        d = warp_sum(d);
        float sc = d * qinv * g_minv[idx];
        if (sc > ts[TOPK-1]){
            ts[TOPK-1]=sc; ti[TOPK-1]=idx;
            #pragma unroll
            for (int r=TOPK-1; r>0; r--){
                if (ts[r] > ts[r-1]){
                    float t=ts[r]; ts[r]=ts[r-1]; ts[r-1]=t;
                    int   u=ti[r]; ti[r]=ti[r-1]; ti[r-1]=u;
                }
            }
        }
    }

    float wv[TOPK], sum=0.f;
    #pragma unroll
    for (int r=0;r<TOPK;r++){ wv[r] = expf(ts[r]-ts[0]); sum += wv[r]; }
    float isum = 1.0f/sum;

    float4 o[4];
    #pragma unroll
    for (int w4=0; w4<4; w4++) o[w4] = xv[w4];
    #pragma unroll
    for (int r=0; r<TOPK; r++){
        float wr = 0.5f * wv[r] * isum;
        const float4* mr = (const float4*)(mem + (size_t)ti[r]*CDIM);
        #pragma unroll
        for (int w4=0; w4<4; w4++){
            float4 mv = mr[lane + w4*32];
            o[w4].x += wr*mv.x; o[w4].y += wr*mv.y;
            o[w4].z += wr*mv.z; o[w4].w += wr*mv.w;
        }
    }
    float4* orow = (float4*)(out + (size_t)gw*CDIM);
    #pragma unroll
    for (int w4=0; w4<4; w4++) orow[lane + w4*32] = o[w4];
}

// ---------------------------------------------------------------------------
extern "C" void kernel_launch(void* const* d_in, const int* in_sizes, int n_in,
                              void* d_out, int out_size){
    const float* x   = (const float*)d_in[0];   // [4,2048,512]
    const float* mem = (const float*)d_in[1];   // [32768,512]
    float* out = (float*)d_out;

    cudaFuncSetAttribute(sim_topk_kernel,
                         cudaFuncAttributeMaxDynamicSharedMemorySize, SMEM_BYTES);

    normalize_kernel<0><<<NQ/8, 256>>>(x);
    normalize_kernel<1><<<MROWS/8, 256>>>(mem);
    sim_topk_kernel<<<dim3(NCH, NQ/QT), 256, SMEM_BYTES>>>();
    merge_kernel<<<(NQ*32)/256, 256>>>(x, mem, out);
}

// round 3
// speedup vs baseline: 1.0009x; 1.0009x over previous
#include <cuda_runtime.h>
#include <cuda_bf16.h>
#include <cstdint>

// Problem constants
#define NQ      8192        // B*S queries
#define CDIM    512         // feature dim (K of the GEMM)
#define MROWS   32768       // memory table rows
#define TOPK    5
#define NCH     8           // M chunks (candidate stage)
#define MCHUNK  (MROWS/NCH) // 4096
#define NCAND   (NCH*TOPK)  // 40

// GEMM tiling
#define QT        128       // queries per block
#define NT        64        // memory rows per inner tile
#define KC        64        // k-chunk for M tile streaming
#define NKC       (CDIM/KC) // 8
#define MT_PER    (MCHUNK/NT) // 64
#define SQ_STRIDE 520       // bf16 elems per sQ row (512 + 8 pad)
#define SM_STRIDE 72        // bf16 elems per sM row (64 + 8 pad)
#define SS_STRIDE 65        // floats per sSim row (64 + 1 pad)

#define SMEM_BYTES (QT*SQ_STRIDE*2 + 2*NT*SM_STRIDE*2 + QT*SS_STRIDE*4) // 184832

// Scratch (device globals: allocation-free)
__device__ __nv_bfloat16 g_qn[(size_t)NQ*CDIM];
__device__ __nv_bfloat16 g_mn[(size_t)MROWS*CDIM];
__device__ float g_minv[MROWS];
__device__ float g_cscore[(size_t)NQ*NCAND];
__device__ int   g_cidx[(size_t)NQ*NCAND];

__device__ __forceinline__ uint32_t smem_u32(const void* p){
    return (uint32_t)__cvta_generic_to_shared(p);
}
__device__ __forceinline__ float warp_sum(float v){
    #pragma unroll
    for (int o=16;o;o>>=1) v += __shfl_xor_sync(0xffffffffu, v, o);
    return v;
}

// ---------------------------------------------------------------------------
// Kernel 1/2: L2-normalize rows (fp32 in -> bf16 out). MODE 0: queries, 1: memory.
// One warp per row; 256 threads = 8 rows/block.
// ---------------------------------------------------------------------------
template<int MODE>
__global__ void normalize_kernel(const float* __restrict__ in){
    const int rows = MODE ? MROWS : NQ;
    __nv_bfloat16* outb = MODE ? g_mn : g_qn;
    int row  = blockIdx.x*8 + (threadIdx.x >> 5);
    int lane = threadIdx.x & 31;
    if (row >= rows) return;
    const float4* src = (const float4*)(in + (size_t)row*CDIM);
    float4 v[4];
    float ss = 0.f;
    #pragma unroll
    for (int w=0; w<4; w++){
        v[w] = src[lane + w*32];
        ss += v[w].x*v[w].x + v[w].y*v[w].y + v[w].z*v[w].z + v[w].w*v[w].w;
    }
    ss = warp_sum(ss);
    float inv = 1.0f / fmaxf(sqrtf(ss), 1e-12f);
    __nv_bfloat16* dst = outb + (size_t)row*CDIM;
    #pragma unroll
    for (int w=0; w<4; w++){
        __nv_bfloat162 p0 = __floats2bfloat162_rn(v[w].x*inv, v[w].y*inv);
        __nv_bfloat162 p1 = __floats2bfloat162_rn(v[w].z*inv, v[w].w*inv);
        uint2 st;
        st.x = *(uint32_t*)&p0;
        st.y = *(uint32_t*)&p1;
        *(uint2*)(dst + (lane + w*32)*4) = st;
    }
    if (MODE && lane==0) g_minv[row] = inv;
}

// ---------------------------------------------------------------------------
// Kernel 3: fused bf16 HMMA GEMM (128q x 4096m per block, K=512) + streaming
// per-chunk top-5. grid = (NCH, NQ/QT). Q tile lives in SMEM for full K.
// ---------------------------------------------------------------------------
__global__ void __launch_bounds__(256,1) sim_topk_kernel(){
    extern __shared__ __align__(16) char smraw[];
    __nv_bfloat16* sQ  = (__nv_bfloat16*)smraw;
    __nv_bfloat16* sM  = (__nv_bfloat16*)(smraw + QT*SQ_STRIDE*2);
    float*         sSim= (float*)(smraw + QT*SQ_STRIDE*2 + 2*NT*SM_STRIDE*2);

    const int tid  = threadIdx.x;
    const int lane = tid & 31;
    const int wid  = tid >> 5;
    const int chunk = blockIdx.x;
    const int qbase = blockIdx.y * QT;
    const int mbase = chunk * MCHUNK;

    // Load Q tile (128 x 512 bf16) into SMEM, padded rows (conflict-free ldmatrix).
    const uint4* gq = (const uint4*)g_qn;   // 8 bf16 per uint4, 64 per row
    #pragma unroll
    for (int i=0; i<(QT*64)/256; i++){
        int idx = tid + i*256;
        int r = idx >> 6, c = idx & 63;
        uint4 val = gq[(size_t)(qbase + r)*64 + c];
        *(uint4*)(sQ + r*SQ_STRIDE + c*8) = val;
    }

    const int wq = (wid & 1) * 64;   // warp's 64-query slab
    const int wn = (wid >> 1) * 16;  // warp's 16-memory-col slab

    // Running top-5 (only threads < 128 use it; kept in registers)
    float s0=-2.f,s1=-2.f,s2=-2.f,s3=-2.f,s4=-2.f;
    int   i0=0,i1=0,i2=0,i3=0,i4=0;

    const uint4* gm = (const uint4*)g_mn;
    const int r0 = tid >> 3,       c0 = tid & 7;  // 512 uint4 per M-tile k-chunk: 2/thread
    const int r1 = (tid+256) >> 3;                // second item, same c

    __syncthreads();

    for (int mt=0; mt<MT_PER; mt++){
        const int mrow0 = mbase + mt*NT;
        float acc[4][2][4];
        #pragma unroll
        for (int a=0;a<4;a++)
            #pragma unroll
            for (int b=0;b<2;b++)
                #pragma unroll
                for (int d=0;d<4;d++) acc[a][b][d]=0.f;

        // Prefetch k-chunk 0 into regs, stage to buffer 0
        uint4 pa = gm[(size_t)(mrow0+r0)*64 + c0];
        uint4 pb = gm[(size_t)(mrow0+r1)*64 + c0];
        *(uint4*)(sM + r0*SM_STRIDE + c0*8) = pa;
        *(uint4*)(sM + r1*SM_STRIDE + c0*8) = pb;
        __syncthreads();

        #pragma unroll
        for (int kc=0; kc<NKC; kc++){
            if (kc+1 < NKC){
                pa = gm[(size_t)(mrow0+r0)*64 + (kc+1)*8 + c0];
                pb = gm[(size_t)(mrow0+r1)*64 + (kc+1)*8 + c0];
            }
            const __nv_bfloat16* mb = sM + (kc & 1)*(NT*SM_STRIDE);
            #pragma unroll
            for (int k16=0; k16<KC/16; k16++){
                // B fragments: memory rows are k-contiguous == col-major B. No .trans.
                uint32_t bfr[2][2];
                #pragma unroll
                for (int nt=0; nt<2; nt++){
                    int brow = wn + nt*8 + (lane & 7);
                    int bk   = k16*16 + ((lane >> 3) & 1)*8;
                    uint32_t ba = smem_u32(mb + brow*SM_STRIDE + bk);
                    asm volatile("ldmatrix.sync.aligned.m8n8.x2.shared.b16 {%0,%1}, [%2];"
                                 : "=r"(bfr[nt][0]), "=r"(bfr[nt][1]) : "r"(ba));
                }
                #pragma unroll
                for (int qt=0; qt<4; qt++){
                    uint32_t a0,a1,a2,a3;
                    int arow = wq + qt*16 + (lane & 15);
                    int ak   = kc*KC + k16*16 + (lane >> 4)*8;
                    uint32_t aa = smem_u32(sQ + arow*SQ_STRIDE + ak);
                    asm volatile("ldmatrix.sync.aligned.m8n8.x4.shared.b16 {%0,%1,%2,%3}, [%4];"
                                 : "=r"(a0),"=r"(a1),"=r"(a2),"=r"(a3) : "r"(aa));
                    #pragma unroll
                    for (int nt=0; nt<2; nt++){
                        asm volatile(
                          "mma.sync.aligned.m16n8k16.row.col.f32.bf16.bf16.f32 "
                          "{%0,%1,%2,%3}, {%4,%5,%6,%7}, {%8,%9}, {%0,%1,%2,%3};"
                          : "+f"(acc[qt][nt][0]),"+f"(acc[qt][nt][1]),
                            "+f"(acc[qt][nt][2]),"+f"(acc[qt][nt][3])
                          : "r"(a0),"r"(a1),"r"(a2),"r"(a3),
                            "r"(bfr[nt][0]),"r"(bfr[nt][1]));
                    }
                }
            }
            if (kc+1 < NKC){
                __nv_bfloat16* db = sM + ((kc+1)&1)*(NT*SM_STRIDE);
                *(uint4*)(db + r0*SM_STRIDE + c0*8) = pa;
                *(uint4*)(db + r1*SM_STRIDE + c0*8) = pb;
            }
            __syncthreads();
        }

        // Spill 128x64 score tile to SMEM (mma D-fragment layout).
        #pragma unroll
        for (int qt=0; qt<4; qt++){
            #pragma unroll
            for (int nt=0; nt<2; nt++){
                int r = wq + qt*16 + (lane >> 2);
                int c = wn + nt*8  + (lane & 3)*2;
                sSim[r*SS_STRIDE + c]         = acc[qt][nt][0];
                sSim[r*SS_STRIDE + c + 1]     = acc[qt][nt][1];
                sSim[(r+8)*SS_STRIDE + c]     = acc[qt][nt][2];
                sSim[(r+8)*SS_STRIDE + c + 1] = acc[qt][nt][3];
            }
        }
        __syncthreads();

        // 128 scan threads update running top-5 (strict >, earlier index wins ties).
        if (tid < QT){
            const float* row = sSim + tid*SS_STRIDE;
            #pragma unroll 4
            for (int c=0; c<NT; c++){
                float v = row[c];
                int id = mrow0 + c;
                if (v > s4){
                    if (v > s2){
                        if (v > s1){
                            if (v > s0){ s4=s3;i4=i3; s3=s2;i3=i2; s2=s1;i2=i1; s1=s0;i1=i0; s0=v;i0=id; }
                            else       { s4=s3;i4=i3; s3=s2;i3=i2; s2=s1;i2=i1; s1=v;i1=id; }
                        } else         { s4=s3;i4=i3; s3=s2;i3=i2; s2=v;i2=id; }
                    } else {
                        if (v > s3)    { s4=s3;i4=i3; s3=v;i3=id; }
                        else           { s4=v;i4=id; }
                    }
                }
            }
        }
        __syncthreads();
    }

    if (tid < QT){
        int q = qbase + tid;
        float* cs = g_cscore + (size_t)q*NCAND + chunk*TOPK;
        int*   ci = g_cidx   + (size_t)q*NCAND + chunk*TOPK;
        cs[0]=s0; cs[1]=s1; cs[2]=s2; cs[3]=s3; cs[4]=s4;
        ci[0]=i0; ci[1]=i1; ci[2]=i2; ci[3]=i3; ci[4]=i4;
    }
}

// ---------------------------------------------------------------------------
// Kernel 4: exact fp32 rescore of 40 candidates, true top-5, softmax, gather,
// out = x + 0.5 * retrieved. One warp per query.
// ---------------------------------------------------------------------------
__global__ void merge_kernel(const float* __restrict__ x,
                             const float* __restrict__ mem,
                             float* __restrict__ out){
    int gw   = (blockIdx.x*blockDim.x + threadIdx.x) >> 5;
    int lane = threadIdx.x & 31;
    if (gw >= NQ) return;

    const float4* xr = (const float4*)(x + (size_t)gw*CDIM);
    float4 xv[4];
    float ss = 0.f;
    #pragma unroll
    for (int w=0; w<4; w++){
        xv[w] = xr[lane + w*32];
        ss += xv[w].x*xv[w].x + xv[w].y*xv[w].y + xv[w].z*xv[w].z + xv[w].w*xv[w].w;
    }
    ss = warp_sum(ss);
    float qinv = 1.0f / fmaxf(sqrtf(ss), 1e-12f);

    float ts[TOPK]; int ti[TOPK];
    #pragma unroll
    for (int r=0;r<TOPK;r++){ ts[r]=-2.f; ti[r]=0; }

    for (int c=0; c<NCAND; c++){
        int idx = g_cidx[(size_t)gw*NCAND + c];
        const float4* mr = (const float4*)(mem + (size_t)idx*CDIM);
        float d = 0.f;
        #pragma unroll
        for (int w=0; w<4; w++){
            float4 mv = mr[lane + w*32];
            d += xv[w].x*mv.x + xv[w].y*mv.y + xv[w].z*mv.z + xv[w].w*mv.w;
        }
        d = warp_sum(d);
        float sc = d * qinv * g_minv[idx];
        if (sc > ts[TOPK-1]){
            ts[TOPK-1]=sc; ti[TOPK-1]=idx;
            #pragma unroll
            for (int r=TOPK-1; r>0; r--){
                if (ts[r] > ts[r-1]){
                    float t=ts[r]; ts[r]=ts[r-1]; ts[r-1]=t;
                    int   u=ti[r]; ti[r]=ti[r-1]; ti[r-1]=u;
                }
            }
        }
    }

    float wv[TOPK], sum=0.f;
    #pragma unroll
    for (int r=0;r<TOPK;r++){ wv[r] = expf(ts[r]-ts[0]); sum += wv[r]; }
    float isum = 1.0f/sum;

    float4 o[4];
    #pragma unroll
    for (int w4=0; w4<4; w4++) o[w4] = xv[w4];
    #pragma unroll
    for (int r=0; r<TOPK; r++){
        float wr = 0.5f * wv[r] * isum;
        const float4* mr = (const float4*)(mem + (size_t)ti[r]*CDIM);
        #pragma unroll
        for (int w4=0; w4<4; w4++){
            float4 mv = mr[lane + w4*32];
            o[w4].x += wr*mv.x; o[w4].y += wr*mv.y;
            o[w4].z += wr*mv.z; o[w4].w += wr*mv.w;
        }
    }
    float4* orow = (float4*)(out + (size_t)gw*CDIM);
    #pragma unroll
    for (int w4=0; w4<4; w4++) orow[lane + w4*32] = o[w4];
}

// ---------------------------------------------------------------------------
extern "C" void kernel_launch(void* const* d_in, const int* in_sizes, int n_in,
                              void* d_out, int out_size){
    const float* x   = (const float*)d_in[0];   // [4,2048,512]
    const float* mem = (const float*)d_in[1];   // [32768,512]
    float* out = (float*)d_out;

    cudaFuncSetAttribute(sim_topk_kernel,
                         cudaFuncAttributeMaxDynamicSharedMemorySize, SMEM_BYTES);

    normalize_kernel<0><<<NQ/8, 256>>>(x);
    normalize_kernel<1><<<MROWS/8, 256>>>(mem);
    sim_topk_kernel<<<dim3(NCH, NQ/QT), 256, SMEM_BYTES>>>();
    merge_kernel<<<(NQ*32)/256, 256>>>(x, mem, out);
}

// round 5
// speedup vs baseline: 1.3059x; 1.3047x over previous
#include <cuda_runtime.h>
#include <cuda_bf16.h>
#include <cstdint>

// Problem constants
#define NQ      8192
#define CDIM    512
#define MROWS   32768
#define TOPK    5
#define NCH     8
#define MCHUNK  (MROWS/NCH)   // 4096
#define NCAND   (NCH*TOPK)    // 40

// GEMM tiling (family-common ISA: mma.sync + ldmatrix + cp.async)
#define QT        128         // queries per block
#define NT        128         // memory rows per tile
#define MT_PER    (MCHUNK/NT) // 32 tiles per block
#define KC        64          // k elements per staged chunk
#define NKC       (CDIM/KC)   // 8
#define NCHUNKS   (MT_PER*NKC)// 256
#define NSTAGE    3

#define SQ_STRIDE 520                          // bf16 (512 + 8 pad) -> 1040B rows
#define SM_STRIDE 72                           // bf16 (64 + 8 pad)  -> 144B rows
#define SS_STRIDE 132                          // bf16 (128 + 4 pad) -> 264B rows

#define SQ_BYTES    (QT*SQ_STRIDE*2)           // 133120
#define CHUNK_BYTES (NT*SM_STRIDE*2)           // 18432
#define SM_OFF      SQ_BYTES
#define SS_OFF      (SM_OFF + NSTAGE*CHUNK_BYTES)  // 188416
#define SMEM_BYTES  (SS_OFF + QT*SS_STRIDE*2)      // 222208

// Scratch (device globals: allocation-free)
__device__ __align__(256) __nv_bfloat16 g_qn[(size_t)NQ*CDIM];
__device__ __align__(256) __nv_bfloat16 g_mn[(size_t)MROWS*CDIM];
__device__ float g_minv[MROWS];
__device__ float g_cscore[(size_t)NQ*NCAND];
__device__ int   g_cidx[(size_t)NQ*NCAND];

__device__ __forceinline__ uint32_t smem_u32(const void* p){
    return (uint32_t)__cvta_generic_to_shared(p);
}
__device__ __forceinline__ float warp_sum(float v){
    #pragma unroll
    for (int o=16;o;o>>=1) v += __shfl_xor_sync(0xffffffffu, v, o);
    return v;
}
__device__ __forceinline__ void cp_async16(uint32_t dst, const void* src){
    asm volatile("cp.async.cg.shared.global [%0], [%1], 16;"
                 :: "r"(dst), "l"(src) : "memory");
}
__device__ __forceinline__ void cp_commit(){
    asm volatile("cp.async.commit_group;" ::: "memory");
}
template<int N>
__device__ __forceinline__ void cp_wait(){
    asm volatile("cp.async.wait_group %0;" :: "n"(N) : "memory");
}

// ---------------------------------------------------------------------------
// Kernel 1/2: L2-normalize rows (fp32 in -> bf16 out). MODE 0: queries, 1: memory.
// ---------------------------------------------------------------------------
template<int MODE>
__global__ void normalize_kernel(const float* __restrict__ in){
    const int rows = MODE ? MROWS : NQ;
    __nv_bfloat16* outb = MODE ? g_mn : g_qn;
    int row  = blockIdx.x*8 + (threadIdx.x >> 5);
    int lane = threadIdx.x & 31;
    if (row >= rows) return;
    const float4* src = (const float4*)(in + (size_t)row*CDIM);
    float4 v[4];
    float ss = 0.f;
    #pragma unroll
    for (int w=0; w<4; w++){
        v[w] = src[lane + w*32];
        ss += v[w].x*v[w].x + v[w].y*v[w].y + v[w].z*v[w].z + v[w].w*v[w].w;
    }
    ss = warp_sum(ss);
    float inv = 1.0f / fmaxf(sqrtf(ss), 1e-12f);
    __nv_bfloat16* dst = outb + (size_t)row*CDIM;
    #pragma unroll
    for (int w=0; w<4; w++){
        __nv_bfloat162 p0 = __floats2bfloat162_rn(v[w].x*inv, v[w].y*inv);
        __nv_bfloat162 p1 = __floats2bfloat162_rn(v[w].z*inv, v[w].w*inv);
        uint2 st;
        st.x = *(uint32_t*)&p0;
        st.y = *(uint32_t*)&p1;
        *(uint2*)(dst + (lane + w*32)*4) = st;
    }
    if (MODE && lane==0) g_minv[row] = inv;
}

// ---------------------------------------------------------------------------
// Kernel 3: bf16 HMMA GEMM (128q x 128m tiles, K=512 resident Q) + streaming
// per-chunk top-5. grid = (NCH, NQ/QT), 256 threads.
//   - Q tile (128x512 bf16) resident in SMEM (padded stride, conflict-free).
//   - M streamed as 128x64 k-chunks through a 3-stage cp.async ring.
//   - warp layout: wq = (wid&1)*64 (4 m16 tiles), wn = (wid>>1)*32 (4 n8 tiles)
//     -> 64 fp32 accumulators, A fragment reused across 4 N tiles.
//   - score tile spilled as bf16 (selection only; merge rescores exact fp32),
//     128 threads keep running register top-5 per query row.
// ---------------------------------------------------------------------------
__global__ void __launch_bounds__(256,1) sim_topk_hmma(){
    extern __shared__ __align__(16) char sm[];
    __nv_bfloat16* sQ = (__nv_bfloat16*)sm;

    const int tid  = threadIdx.x;
    const int lane = tid & 31;
    const int wid  = tid >> 5;
    const int chunk = blockIdx.x;
    const int qbase = blockIdx.y * QT;
    const int mbase = chunk * MCHUNK;

    // ---- Load resident Q tile (128 x 512 bf16, padded rows) ----
    {
        const uint4* gq = (const uint4*)g_qn;   // 64 uint4 per row
        #pragma unroll
        for (int i=0; i<(QT*64)/256; i++){
            int idx = tid + i*256;
            int r = idx >> 6, c = idx & 63;
            uint4 v = gq[(size_t)(qbase + r)*64 + c];
            *(uint4*)(sQ + r*SQ_STRIDE + c*8) = v;
        }
    }

    // ---- producer state: each thread copies 4x16B per chunk ----
    const int rowt = tid >> 3;          // 0..31 (rows rowt + 32i)
    const int c8   = tid & 7;           // 16B column
    const __nv_bfloat16* gmb = g_mn;

    auto issue_chunk = [&](int cidx, int stage){
        int mt = cidx >> 3, kc = cidx & 7;
        const __nv_bfloat16* src = gmb
            + (size_t)(mbase + mt*NT + rowt)*CDIM + kc*KC + c8*8;
        uint32_t dst = smem_u32(sm + SM_OFF + stage*CHUNK_BYTES
                                + rowt*(SM_STRIDE*2) + c8*16);
        #pragma unroll
        for (int i=0; i<4; i++)
            cp_async16(dst + i*32*(SM_STRIDE*2), src + (size_t)i*32*CDIM);
    };

    // prologue: stages 0,1
    issue_chunk(0, 0); cp_commit();
    issue_chunk(1, 1); cp_commit();

    const int wq = (wid & 1) * 64;      // warp's 64-query slab
    const int wn = (wid >> 1) * 32;     // warp's 32-memory-col slab

    // running top-5 (threads < 128)
    float s0=-2.f,s1=-2.f,s2=-2.f,s3=-2.f,s4=-2.f;
    int   i0=0,i1=0,i2=0,i3=0,i4=0;

    int s_cons = 0, s_prod = 2;         // ring cursors (mod 3)

    for (int mt=0; mt<MT_PER; mt++){
        float acc[4][4][4];
        #pragma unroll
        for (int a=0;a<4;a++)
            #pragma unroll
            for (int b=0;b<4;b++)
                #pragma unroll
                for (int d=0;d<4;d++) acc[a][b][d]=0.f;

        #pragma unroll 1
        for (int kc=0; kc<NKC; kc++){
            const int cidx = mt*NKC + kc;
            cp_wait<1>();
            __syncthreads();
            if (cidx + 2 < NCHUNKS) issue_chunk(cidx + 2, s_prod);
            cp_commit();
            if (++s_prod == NSTAGE) s_prod = 0;

            const __nv_bfloat16* mb = (const __nv_bfloat16*)
                (sm + SM_OFF + s_cons*CHUNK_BYTES);
            if (++s_cons == NSTAGE) s_cons = 0;

            #pragma unroll
            for (int k16=0; k16<KC/16; k16++){
                // B fragments: 2 ldmatrix.x4, each covers two n8 tiles.
                uint32_t bfr[4][2];
                #pragma unroll
                for (int ntp=0; ntp<2; ntp++){
                    int brow = wn + ntp*16 + ((lane>>4)&1)*8 + (lane&7);
                    int bk   = k16*16 + ((lane>>3)&1)*8;
                    uint32_t ba = smem_u32(mb + brow*SM_STRIDE + bk);
                    asm volatile("ldmatrix.sync.aligned.m8n8.x4.shared.b16 {%0,%1,%2,%3}, [%4];"
                                 : "=r"(bfr[ntp*2][0]),   "=r"(bfr[ntp*2][1]),
                                   "=r"(bfr[ntp*2+1][0]), "=r"(bfr[ntp*2+1][1]) : "r"(ba));
                }
                #pragma unroll
                for (int qt=0; qt<4; qt++){
                    uint32_t a0,a1,a2,a3;
                    int arow = wq + qt*16 + (lane & 15);
                    int ak   = kc*KC + k16*16 + (lane >> 4)*8;
                    uint32_t aa = smem_u32(sQ + arow*SQ_STRIDE + ak);
                    asm volatile("ldmatrix.sync.aligned.m8n8.x4.shared.b16 {%0,%1,%2,%3}, [%4];"
                                 : "=r"(a0),"=r"(a1),"=r"(a2),"=r"(a3) : "r"(aa));
                    #pragma unroll
                    for (int nt=0; nt<4; nt++){
                        asm volatile(
                          "mma.sync.aligned.m16n8k16.row.col.f32.bf16.bf16.f32 "
                          "{%0,%1,%2,%3}, {%4,%5,%6,%7}, {%8,%9}, {%0,%1,%2,%3};"
                          : "+f"(acc[qt][nt][0]),"+f"(acc[qt][nt][1]),
                            "+f"(acc[qt][nt][2]),"+f"(acc[qt][nt][3])
                          : "r"(a0),"r"(a1),"r"(a2),"r"(a3),
                            "r"(bfr[nt][0]),"r"(bfr[nt][1]));
                    }
                }
            }
        }

        // ---- spill 128x128 score tile as bf16 (selection only) ----
        __nv_bfloat16* sS = (__nv_bfloat16*)(sm + SS_OFF);
        #pragma unroll
        for (int qt=0; qt<4; qt++){
            #pragma unroll
            for (int nt=0; nt<4; nt++){
                int r = wq + qt*16 + (lane >> 2);
                int c = wn + nt*8  + (lane & 3)*2;
                __nv_bfloat162 p0 = __floats2bfloat162_rn(acc[qt][nt][0], acc[qt][nt][1]);
                __nv_bfloat162 p1 = __floats2bfloat162_rn(acc[qt][nt][2], acc[qt][nt][3]);
                *(uint32_t*)(sS + r*SS_STRIDE + c)     = *(uint32_t*)&p0;
                *(uint32_t*)(sS + (r+8)*SS_STRIDE + c) = *(uint32_t*)&p1;
            }
        }
        __syncthreads();

        // ---- 128 scan threads update running top-5 ----
        if (tid < QT){
            const int mrow0 = mbase + mt*NT;
            const uint32_t* row = (const uint32_t*)(sS + tid*SS_STRIDE);
            #pragma unroll 4
            for (int j=0; j<NT/2; j++){
                uint32_t pr = row[j];
                float2 vf = __bfloat1622float2(*(__nv_bfloat162*)&pr);
                #pragma unroll
                for (int h=0; h<2; h++){
                    float v = h ? vf.y : vf.x;
                    int id = mrow0 + 2*j + h;
                    if (v > s4){
                        if (v > s2){
                            if (v > s1){
                                if (v > s0){ s4=s3;i4=i3; s3=s2;i3=i2; s2=s1;i2=i1; s1=s0;i1=i0; s0=v;i0=id; }
                                else       { s4=s3;i4=i3; s3=s2;i3=i2; s2=s1;i2=i1; s1=v;i1=id; }
                            } else         { s4=s3;i4=i3; s3=s2;i3=i2; s2=v;i2=id; }
                        } else {
                            if (v > s3)    { s4=s3;i4=i3; s3=v;i3=id; }
                            else           { s4=v;i4=id; }
                        }
                    }
                }
            }
        }
        // next-tile kc-loop syncs order scan vs. next spill; no extra sync.
    }

    if (tid < QT){
        int q = qbase + tid;
        float* cs = g_cscore + (size_t)q*NCAND + chunk*TOPK;
        int*   ci = g_cidx   + (size_t)q*NCAND + chunk*TOPK;
        cs[0]=s0; cs[1]=s1; cs[2]=s2; cs[3]=s3; cs[4]=s4;
        ci[0]=i0; ci[1]=i1; ci[2]=i2; ci[3]=i3; ci[4]=i4;
    }
}

// ---------------------------------------------------------------------------
// Kernel 4: exact fp32 rescore of 40 candidates, true top-5, softmax, gather,
// out = x + 0.5 * retrieved. One warp per query.
// ---------------------------------------------------------------------------
__global__ void merge_kernel(const float* __restrict__ x,
                             const float* __restrict__ mem,
                             float* __restrict__ out){
    int gw   = (blockIdx.x*blockDim.x + threadIdx.x) >> 5;
    int lane = threadIdx.x & 31;
    if (gw >= NQ) return;

    const float4* xr = (const float4*)(x + (size_t)gw*CDIM);
    float4 xv[4];
    float ss = 0.f;
    #pragma unroll
    for (int w=0; w<4; w++){
        xv[w] = xr[lane + w*32];
        ss += xv[w].x*xv[w].x + xv[w].y*xv[w].y + xv[w].z*xv[w].z + xv[w].w*xv[w].w;
    }
    ss = warp_sum(ss);
    float qinv = 1.0f / fmaxf(sqrtf(ss), 1e-12f);

    float ts[TOPK]; int ti[TOPK];
    #pragma unroll
    for (int r=0;r<TOPK;r++){ ts[r]=-2.f; ti[r]=0; }

    for (int c=0; c<NCAND; c++){
        int idx = g_cidx[(size_t)gw*NCAND + c];
        const float4* mr = (const float4*)(mem + (size_t)idx*CDIM);
        float d = 0.f;
        #pragma unroll
        for (int w=0; w<4; w++){
            float4 mv = mr[lane + w*32];
            d += xv[w].x*mv.x + xv[w].y*mv.y + xv[w].z*mv.z + xv[w].w*mv.w;
        }
        d = warp_sum(d);
        float sc = d * qinv * g_minv[idx];
        if (sc > ts[TOPK-1]){
            ts[TOPK-1]=sc; ti[TOPK-1]=idx;
            #pragma unroll
            for (int r=TOPK-1; r>0; r--){
                if (ts[r] > ts[r-1]){
                    float t=ts[r]; ts[r]=ts[r-1]; ts[r-1]=t;
                    int   u=ti[r]; ti[r]=ti[r-1]; ti[r-1]=u;
                }
            }
        }
    }

    float wv[TOPK], sum=0.f;
    #pragma unroll
    for (int r=0;r<TOPK;r++){ wv[r] = expf(ts[r]-ts[0]); sum += wv[r]; }
    float isum = 1.0f/sum;

    float4 o[4];
    #pragma unroll
    for (int w4=0; w4<4; w4++) o[w4] = xv[w4];
    #pragma unroll
    for (int r=0; r<TOPK; r++){
        float wr = 0.5f * wv[r] * isum;
        const float4* mr = (const float4*)(mem + (size_t)ti[r]*CDIM);
        #pragma unroll
        for (int w4=0; w4<4; w4++){
            float4 mv = mr[lane + w4*32];
            o[w4].x += wr*mv.x; o[w4].y += wr*mv.y;
            o[w4].z += wr*mv.z; o[w4].w += wr*mv.w;
        }
    }
    float4* orow = (float4*)(out + (size_t)gw*CDIM);
    #pragma unroll
    for (int w4=0; w4<4; w4++) orow[lane + w4*32] = o[w4];
}

// ---------------------------------------------------------------------------
extern "C" void kernel_launch(void* const* d_in, const int* in_sizes, int n_in,
                              void* d_out, int out_size){
    const float* x   = (const float*)d_in[0];   // [4,2048,512]
    const float* mem = (const float*)d_in[1];   // [32768,512]
    float* out = (float*)d_out;

    cudaFuncSetAttribute(sim_topk_hmma,
                         cudaFuncAttributeMaxDynamicSharedMemorySize, SMEM_BYTES);

    normalize_kernel<0><<<NQ/8, 256>>>(x);
    normalize_kernel<1><<<MROWS/8, 256>>>(mem);
    sim_topk_hmma<<<dim3(NCH, NQ/QT), 256, SMEM_BYTES>>>();
    merge_kernel<<<(NQ*32)/256, 256>>>(x, mem, out);
}

// round 6
// speedup vs baseline: 1.3325x; 1.0203x over previous
#include <cuda_runtime.h>
#include <cuda_bf16.h>
#include <cstdint>

// Problem constants
#define NQ      8192
#define CDIM    512
#define MROWS   32768
#define TOPK    5
#define NCH     8
#define MCHUNK  (MROWS/NCH)   // 4096
#define NCAND   (NCH*TOPK)    // 40

// GEMM tiling (family-common ISA: fp8 mma.sync m16n8k32 + ldmatrix + cp.async)
#define QT        128         // queries per block
#define NT        128         // memory rows per tile
#define MT_PER    (MCHUNK/NT) // 32 tiles per block
#define KC        128         // k elements (fp8) per staged chunk
#define NKC       (CDIM/KC)   // 4
#define NCHUNKS   (MT_PER*NKC)// 128
#define NSTAGE    3

#define SQ_STRIDE 528                          // bytes per sQ row (512 + 16 pad)
#define SM_STRIDE 144                          // bytes per sM row (128 + 16 pad)
#define SS_STRIDE 132                          // bf16 elems per sSim row (128 + 4)

#define SQ_BYTES    (QT*SQ_STRIDE)             // 67584
#define CHUNK_BYTES (NT*SM_STRIDE)             // 18432
#define SM_OFF      SQ_BYTES
#define SS_OFF      (SM_OFF + NSTAGE*CHUNK_BYTES)  // 122880
#define SMEM_BYTES  (SS_OFF + QT*SS_STRIDE*2)      // 156672

// Scratch (device globals: allocation-free)
__device__ __align__(256) uint8_t g_qn8[(size_t)NQ*CDIM];     // e4m3 normalized queries
__device__ __align__(256) uint8_t g_mn8[(size_t)MROWS*CDIM];  // e4m3 normalized memory
__device__ float g_minv[MROWS];
__device__ float g_cscore[(size_t)NQ*NCAND];
__device__ int   g_cidx[(size_t)NQ*NCAND];

__device__ __forceinline__ uint32_t smem_u32(const void* p){
    return (uint32_t)__cvta_generic_to_shared(p);
}
__device__ __forceinline__ float warp_sum(float v){
    #pragma unroll
    for (int o=16;o;o>>=1) v += __shfl_xor_sync(0xffffffffu, v, o);
    return v;
}
__device__ __forceinline__ void cp_async16(uint32_t dst, const void* src){
    asm volatile("cp.async.cg.shared.global [%0], [%1], 16;"
                 :: "r"(dst), "l"(src) : "memory");
}
__device__ __forceinline__ void cp_commit(){
    asm volatile("cp.async.commit_group;" ::: "memory");
}
template<int N>
__device__ __forceinline__ void cp_wait(){
    asm volatile("cp.async.wait_group %0;" :: "n"(N) : "memory");
}
// pack 2 floats -> e4m3x2 (a -> upper byte, b -> lower byte)
__device__ __forceinline__ uint16_t f2_e4m3x2(float a, float b){
    uint16_t r;
    asm("cvt.rn.satfinite.e4m3x2.f32 %0, %1, %2;" : "=h"(r) : "f"(a), "f"(b));
    return r;
}

// ---------------------------------------------------------------------------
// Kernel 1/2: L2-normalize rows (fp32 in -> e4m3 out). MODE 0: queries, 1: memory.
// ---------------------------------------------------------------------------
template<int MODE>
__global__ void normalize_kernel(const float* __restrict__ in){
    const int rows = MODE ? MROWS : NQ;
    uint8_t* outb = MODE ? g_mn8 : g_qn8;
    int row  = blockIdx.x*8 + (threadIdx.x >> 5);
    int lane = threadIdx.x & 31;
    if (row >= rows) return;
    const float4* src = (const float4*)(in + (size_t)row*CDIM);
    float4 v[4];
    float ss = 0.f;
    #pragma unroll
    for (int w=0; w<4; w++){
        v[w] = src[lane + w*32];
        ss += v[w].x*v[w].x + v[w].y*v[w].y + v[w].z*v[w].z + v[w].w*v[w].w;
    }
    ss = warp_sum(ss);
    float inv = 1.0f / fmaxf(sqrtf(ss), 1e-12f);
    uint8_t* dst = outb + (size_t)row*CDIM;
    #pragma unroll
    for (int w=0; w<4; w++){
        uint32_t lo = f2_e4m3x2(v[w].y*inv, v[w].x*inv);   // bytes [x,y]
        uint32_t hi = f2_e4m3x2(v[w].w*inv, v[w].z*inv);   // bytes [z,w]
        *(uint32_t*)(dst + (lane + w*32)*4) = lo | (hi << 16);
    }
    if (MODE && lane==0) g_minv[row] = inv;
}

// ---------------------------------------------------------------------------
// Kernel 3: e4m3 mma.sync GEMM (128q x 128m tiles, K=512 resident Q) +
// streaming per-chunk top-5. grid = (NCH, NQ/QT), 256 threads.
//   - Q tile (128x512 fp8) resident in SMEM (padded stride, conflict-free).
//   - M streamed as 128x128(fp8) k-chunks through a 3-stage cp.async ring.
//   - warp layout: wq = (wid&1)*64, wn = (wid>>1)*32 -> 64 fp32 accumulators.
//   - fp8 fragments loaded with ldmatrix.b16 (2 fp8 == 1 b16 unit; layouts
//     coincide for k-contiguous A row-major / B n-major).
//   - score tile spilled as bf16 (selection only; merge rescores exact fp32);
//     scan split across all 256 threads (2 threads per query row).
// ---------------------------------------------------------------------------
__global__ void __launch_bounds__(256,1) sim_topk_fp8(){
    extern __shared__ __align__(16) char sm[];
    uint8_t* sQ = (uint8_t*)sm;

    const int tid  = threadIdx.x;
    const int lane = tid & 31;
    const int wid  = tid >> 5;
    const int chunk = blockIdx.x;
    const int qbase = blockIdx.y * QT;
    const int mbase = chunk * MCHUNK;

    // ---- Load resident Q tile (128 x 512 fp8, padded rows) ----
    {
        const uint4* gq = (const uint4*)g_qn8;   // 32 uint4 per row
        #pragma unroll
        for (int i=0; i<(QT*32)/256; i++){
            int idx = tid + i*256;
            int r = idx >> 5, c = idx & 31;
            uint4 v = gq[(size_t)(qbase + r)*32 + c];
            *(uint4*)(sQ + r*SQ_STRIDE + c*16) = v;
        }
    }

    // ---- producer: each thread copies 4x16B per 128x128 fp8 chunk ----
    const int rowt = tid >> 3;          // 0..31 (rows rowt + 32i)
    const int c16  = tid & 7;           // 16B column (8 per row)
    const uint8_t* gmb = g_mn8;

    auto issue_chunk = [&](int cidx, int stage){
        int mt = cidx >> 2, kc = cidx & 3;
        const uint8_t* src = gmb
            + (size_t)(mbase + mt*NT + rowt)*CDIM + kc*KC + c16*16;
        uint32_t dst = smem_u32(sm + SM_OFF + stage*CHUNK_BYTES
                                + rowt*SM_STRIDE + c16*16);
        #pragma unroll
        for (int i=0; i<4; i++)
            cp_async16(dst + i*32*SM_STRIDE, src + (size_t)i*32*CDIM);
    };

    issue_chunk(0, 0); cp_commit();
    issue_chunk(1, 1); cp_commit();

    const int wq = (wid & 1) * 64;      // warp's 64-query slab
    const int wn = (wid >> 1) * 32;     // warp's 32-memory-col slab

    // running top-5: thread scans row (tid&127), cols [ (tid>>7)*64, +64 )
    const int srow  = tid & 127;
    const int shalf = tid >> 7;
    float s0=-2.f,s1=-2.f,s2=-2.f,s3=-2.f,s4=-2.f;
    int   i0=0,i1=0,i2=0,i3=0,i4=0;

    int s_cons = 0, s_prod = 2;         // ring cursors (mod 3)
    __nv_bfloat16* sS = (__nv_bfloat16*)(sm + SS_OFF);

    for (int mt=0; mt<MT_PER; mt++){
        float acc[4][4][4];
        #pragma unroll
        for (int a=0;a<4;a++)
            #pragma unroll
            for (int b=0;b<4;b++)
                #pragma unroll
                for (int d=0;d<4;d++) acc[a][b][d]=0.f;

        #pragma unroll 1
        for (int kc=0; kc<NKC; kc++){
            const int cidx = mt*NKC + kc;
            cp_wait<1>();
            __syncthreads();
            if (cidx + 2 < NCHUNKS) issue_chunk(cidx + 2, s_prod);
            cp_commit();
            if (++s_prod == NSTAGE) s_prod = 0;

            const uint8_t* mb = (const uint8_t*)(sm + SM_OFF + s_cons*CHUNK_BYTES);
            if (++s_cons == NSTAGE) s_cons = 0;

            #pragma unroll
            for (int k32=0; k32<KC/32; k32++){
                // B fragments: 2 ldmatrix.x4 (b16 view), each covers two n8 tiles
                uint32_t bfr[4][2];
                #pragma unroll
                for (int ntp=0; ntp<2; ntp++){
                    int brow = wn + ntp*16 + ((lane>>4)&1)*8 + (lane&7);
                    int bkB  = k32*32 + ((lane>>3)&1)*16;
                    uint32_t ba = smem_u32(mb + brow*SM_STRIDE + bkB);
                    asm volatile("ldmatrix.sync.aligned.m8n8.x4.shared.b16 {%0,%1,%2,%3}, [%4];"
                                 : "=r"(bfr[ntp*2][0]),   "=r"(bfr[ntp*2][1]),
                                   "=r"(bfr[ntp*2+1][0]), "=r"(bfr[ntp*2+1][1]) : "r"(ba));
                }
                #pragma unroll
                for (int qt=0; qt<4; qt++){
                    uint32_t a0,a1,a2,a3;
                    int arow = wq + qt*16 + (lane & 15);
                    int akB  = kc*KC + k32*32 + (lane >> 4)*16;
                    uint32_t aa = smem_u32(sQ + arow*SQ_STRIDE + akB);
                    asm volatile("ldmatrix.sync.aligned.m8n8.x4.shared.b16 {%0,%1,%2,%3}, [%4];"
                                 : "=r"(a0),"=r"(a1),"=r"(a2),"=r"(a3) : "r"(aa));
                    #pragma unroll
                    for (int nt=0; nt<4; nt++){
                        asm volatile(
                          "mma.sync.aligned.m16n8k32.row.col.f32.e4m3.e4m3.f32 "
                          "{%0,%1,%2,%3}, {%4,%5,%6,%7}, {%8,%9}, {%0,%1,%2,%3};"
                          : "+f"(acc[qt][nt][0]),"+f"(acc[qt][nt][1]),
                            "+f"(acc[qt][nt][2]),"+f"(acc[qt][nt][3])
                          : "r"(a0),"r"(a1),"r"(a2),"r"(a3),
                            "r"(bfr[nt][0]),"r"(bfr[nt][1]));
                    }
                }
            }
        }

        // ---- spill 128x128 score tile as bf16 (selection only) ----
        #pragma unroll
        for (int qt=0; qt<4; qt++){
            #pragma unroll
            for (int nt=0; nt<4; nt++){
                int r = wq + qt*16 + (lane >> 2);
                int c = wn + nt*8  + (lane & 3)*2;
                __nv_bfloat162 p0 = __floats2bfloat162_rn(acc[qt][nt][0], acc[qt][nt][1]);
                __nv_bfloat162 p1 = __floats2bfloat162_rn(acc[qt][nt][2], acc[qt][nt][3]);
                *(uint32_t*)(sS + r*SS_STRIDE + c)     = *(uint32_t*)&p0;
                *(uint32_t*)(sS + (r+8)*SS_STRIDE + c) = *(uint32_t*)&p1;
            }
        }
        __syncthreads();

        // ---- all 256 threads scan: 2 threads/row, 64 cols each ----
        {
            const int mrow0 = mbase + mt*NT + shalf*64;
            const uint32_t* row = (const uint32_t*)(sS + srow*SS_STRIDE + shalf*64);
            #pragma unroll 4
            for (int j=0; j<32; j++){
                uint32_t pr = row[j];
                float2 vf = __bfloat1622float2(*(__nv_bfloat162*)&pr);
                #pragma unroll
                for (int h=0; h<2; h++){
                    float v = h ? vf.y : vf.x;
                    int id = mrow0 + 2*j + h;
                    if (v > s4){
                        if (v > s2){
                            if (v > s1){
                                if (v > s0){ s4=s3;i4=i3; s3=s2;i3=i2; s2=s1;i2=i1; s1=s0;i1=i0; s0=v;i0=id; }
                                else       { s4=s3;i4=i3; s3=s2;i3=i2; s2=s1;i2=i1; s1=v;i1=id; }
                            } else         { s4=s3;i4=i3; s3=s2;i3=i2; s2=v;i2=id; }
                        } else {
                            if (v > s3)    { s4=s3;i4=i3; s3=v;i3=id; }
                            else           { s4=v;i4=id; }
                        }
                    }
                }
            }
        }
        // next-tile kc-loop __syncthreads orders scan vs. next spill
    }

    // ---- merge the two half-row top-5 lists, write candidates ----
    __syncthreads();
    float* stg  = (float*)(sm + SS_OFF);
    int*   stgi = (int*)(stg + 256*TOPK);
    stg[tid*TOPK+0]=s0; stg[tid*TOPK+1]=s1; stg[tid*TOPK+2]=s2; stg[tid*TOPK+3]=s3; stg[tid*TOPK+4]=s4;
    stgi[tid*TOPK+0]=i0; stgi[tid*TOPK+1]=i1; stgi[tid*TOPK+2]=i2; stgi[tid*TOPK+3]=i3; stgi[tid*TOPK+4]=i4;
    __syncthreads();
    if (tid < QT){
        const int o = (tid + 128)*TOPK;
        #pragma unroll
        for (int r=0; r<TOPK; r++){
            float v = stg[o+r]; int id = stgi[o+r];
            if (v > s4){
                if (v > s2){
                    if (v > s1){
                        if (v > s0){ s4=s3;i4=i3; s3=s2;i3=i2; s2=s1;i2=i1; s1=s0;i1=i0; s0=v;i0=id; }
                        else       { s4=s3;i4=i3; s3=s2;i3=i2; s2=s1;i2=i1; s1=v;i1=id; }
                    } else         { s4=s3;i4=i3; s3=s2;i3=i2; s2=v;i2=id; }
                } else {
                    if (v > s3)    { s4=s3;i4=i3; s3=v;i3=id; }
                    else           { s4=v;i4=id; }
                }
            }
        }
        int q = qbase + tid;
        float* cs = g_cscore + (size_t)q*NCAND + chunk*TOPK;
        int*   ci = g_cidx   + (size_t)q*NCAND + chunk*TOPK;
        cs[0]=s0; cs[1]=s1; cs[2]=s2; cs[3]=s3; cs[4]=s4;
        ci[0]=i0; ci[1]=i1; ci[2]=i2; ci[3]=i3; ci[4]=i4;
    }
}

// ---------------------------------------------------------------------------
// Kernel 4: exact fp32 rescore of 40 candidates, true top-5, softmax, gather,
// out = x + 0.5 * retrieved. One warp per query.
// ---------------------------------------------------------------------------
__global__ void merge_kernel(const float* __restrict__ x,
                             const float* __restrict__ mem,
                             float* __restrict__ out){
    int gw   = (blockIdx.x*blockDim.x + threadIdx.x) >> 5;
    int lane = threadIdx.x & 31;
    if (gw >= NQ) return;

    const float4* xr = (const float4*)(x + (size_t)gw*CDIM);
    float4 xv[4];
    float ss = 0.f;
    #pragma unroll
    for (int w=0; w<4; w++){
        xv[w] = xr[lane + w*32];
        ss += xv[w].x*xv[w].x + xv[w].y*xv[w].y + xv[w].z*xv[w].z + xv[w].w*xv[w].w;
    }
    ss = warp_sum(ss);
    float qinv = 1.0f / fmaxf(sqrtf(ss), 1e-12f);

    float ts[TOPK]; int ti[TOPK];
    #pragma unroll
    for (int r=0;r<TOPK;r++){ ts[r]=-2.f; ti[r]=0; }

    for (int c=0; c<NCAND; c++){
        int idx = g_cidx[(size_t)gw*NCAND + c];
        const float4* mr = (const float4*)(mem + (size_t)idx*CDIM);
        float d = 0.f;
        #pragma unroll
        for (int w=0; w<4; w++){
            float4 mv = mr[lane + w*32];
            d += xv[w].x*mv.x + xv[w].y*mv.y + xv[w].z*mv.z + xv[w].w*mv.w;
        }
        d = warp_sum(d);
        float sc = d * qinv * g_minv[idx];
        if (sc > ts[TOPK-1]){
            ts[TOPK-1]=sc; ti[TOPK-1]=idx;
            #pragma unroll
            for (int r=TOPK-1; r>0; r--){
                if (ts[r] > ts[r-1]){
                    float t=ts[r]; ts[r]=ts[r-1]; ts[r-1]=t;
                    int   u=ti[r]; ti[r]=ti[r-1]; ti[r-1]=u;
                }
            }
        }
    }

    float wv[TOPK], sum=0.f;
    #pragma unroll
    for (int r=0;r<TOPK;r++){ wv[r] = expf(ts[r]-ts[0]); sum += wv[r]; }
    float isum = 1.0f/sum;

    float4 o[4];
    #pragma unroll
    for (int w4=0; w4<4; w4++) o[w4] = xv[w4];
    #pragma unroll
    for (int r=0; r<TOPK; r++){
        float wr = 0.5f * wv[r] * isum;
        const float4* mr = (const float4*)(mem + (size_t)ti[r]*CDIM);
        #pragma unroll
        for (int w4=0; w4<4; w4++){
            float4 mv = mr[lane + w4*32];
            o[w4].x += wr*mv.x; o[w4].y += wr*mv.y;
            o[w4].z += wr*mv.z; o[w4].w += wr*mv.w;
        }
    }
    float4* orow = (float4*)(out + (size_t)gw*CDIM);
    #pragma unroll
    for (int w4=0; w4<4; w4++) orow[lane + w4*32] = o[w4];
}

// ---------------------------------------------------------------------------
extern "C" void kernel_launch(void* const* d_in, const int* in_sizes, int n_in,
                              void* d_out, int out_size){
    const float* x   = (const float*)d_in[0];   // [4,2048,512]
    const float* mem = (const float*)d_in[1];   // [32768,512]
    float* out = (float*)d_out;

    cudaFuncSetAttribute(sim_topk_fp8,
                         cudaFuncAttributeMaxDynamicSharedMemorySize, SMEM_BYTES);

    normalize_kernel<0><<<NQ/8, 256>>>(x);
    normalize_kernel<1><<<MROWS/8, 256>>>(mem);
    sim_topk_fp8<<<dim3(NCH, NQ/QT), 256, SMEM_BYTES>>>();
    merge_kernel<<<(NQ*32)/256, 256>>>(x, mem, out);
}

// round 7
// speedup vs baseline: 1.3893x; 1.0427x over previous
#include <cuda_runtime.h>
#include <cuda_bf16.h>
#include <cstdint>

// Problem constants
#define NQ      8192
#define CDIM    512
#define MROWS   32768
#define TOPK    5
#define NCH     8
#define MCHUNK  (MROWS/NCH)   // 4096
#define NCAND   (NCH*TOPK)    // 40

// GEMM tiling (family-common ISA: fp8 mma.sync m16n8k32 + ldmatrix + cp.async)
#define QT        128         // queries per block
#define NT        128         // memory rows per tile
#define MT_PER    (MCHUNK/NT) // 32 tiles per block
#define KC        128         // k elements (fp8) per staged chunk
#define NKC       (CDIM/KC)   // 4
#define NCHUNKS   (MT_PER*NKC)// 128
#define NSTAGE    3
#define CAP       12          // per-row bucket capacity per tile

#define SQ_STRIDE 528                          // bytes per sQ row (512 + 16 pad)
#define SM_STRIDE 144                          // bytes per sM row (128 + 16 pad)
#define SS_STRIDEF 130                         // floats per sSim row (128 + 2)

#define SQ_BYTES    (QT*SQ_STRIDE)             // 67584
#define CHUNK_BYTES (NT*SM_STRIDE)             // 18432
#define SM_OFF      SQ_BYTES
#define SS_OFF      (SM_OFF + NSTAGE*CHUNK_BYTES)   // 122880
#define TH_OFF      (SS_OFF + QT*SS_STRIDEF*4)      // 189440
#define CNT_OFF     (TH_OFF + 512)                  // 189952
#define BS_OFF      (CNT_OFF + 512)                 // 190464
#define BC_OFF      (BS_OFF + QT*CAP*4)             // 196608
#define OVR_OFF     (BC_OFF + QT*CAP*4)             // 202752
#define SMEM_BYTES  (OVR_OFF + 16)

// Scratch (device globals: allocation-free)
__device__ __align__(256) uint8_t g_qn8[(size_t)NQ*CDIM];     // e4m3 normalized queries
__device__ __align__(256) uint8_t g_mn8[(size_t)MROWS*CDIM];  // e4m3 normalized memory
__device__ float g_minv[MROWS];
__device__ int   g_cidx[(size_t)NQ*NCAND];

__device__ __forceinline__ uint32_t smem_u32(const void* p){
    return (uint32_t)__cvta_generic_to_shared(p);
}
__device__ __forceinline__ float warp_sum(float v){
    #pragma unroll
    for (int o=16;o;o>>=1) v += __shfl_xor_sync(0xffffffffu, v, o);
    return v;
}
__device__ __forceinline__ void cp_async16(uint32_t dst, const void* src){
    asm volatile("cp.async.cg.shared.global [%0], [%1], 16;"
                 :: "r"(dst), "l"(src) : "memory");
}
__device__ __forceinline__ void cp_commit(){
    asm volatile("cp.async.commit_group;" ::: "memory");
}
template<int N>
__device__ __forceinline__ void cp_wait(){
    asm volatile("cp.async.wait_group %0;" :: "n"(N) : "memory");
}
// pack 2 floats -> e4m3x2 (a -> upper byte, b -> lower byte)
__device__ __forceinline__ uint16_t f2_e4m3x2(float a, float b){
    uint16_t r;
    asm("cvt.rn.satfinite.e4m3x2.f32 %0, %1, %2;" : "=h"(r) : "f"(a), "f"(b));
    return r;
}

// top-5 insert (strict >, earlier index wins ties)
#define TOP5_INSERT(v, id) do { \
    if ((v) > s4){ \
        if ((v) > s2){ \
            if ((v) > s1){ \
                if ((v) > s0){ s4=s3;i4=i3; s3=s2;i3=i2; s2=s1;i2=i1; s1=s0;i1=i0; s0=(v);i0=(id); } \
                else         { s4=s3;i4=i3; s3=s2;i3=i2; s2=s1;i2=i1; s1=(v);i1=(id); } \
            } else           { s4=s3;i4=i3; s3=s2;i3=i2; s2=(v);i2=(id); } \
        } else { \
            if ((v) > s3)    { s4=s3;i4=i3; s3=(v);i3=(id); } \
            else             { s4=(v);i4=(id); } \
        } \
    } \
} while(0)

// ---------------------------------------------------------------------------
// Kernel 1/2: L2-normalize rows (fp32 in -> e4m3 out). MODE 0: queries, 1: memory.
// ---------------------------------------------------------------------------
template<int MODE>
__global__ void normalize_kernel(const float* __restrict__ in){
    const int rows = MODE ? MROWS : NQ;
    uint8_t* outb = MODE ? g_mn8 : g_qn8;
    int row  = blockIdx.x*8 + (threadIdx.x >> 5);
    int lane = threadIdx.x & 31;
    if (row >= rows) return;
    const float4* src = (const float4*)(in + (size_t)row*CDIM);
    float4 v[4];
    float ss = 0.f;
    #pragma unroll
    for (int w=0; w<4; w++){
        v[w] = src[lane + w*32];
        ss += v[w].x*v[w].x + v[w].y*v[w].y + v[w].z*v[w].z + v[w].w*v[w].w;
    }
    ss = warp_sum(ss);
    float inv = 1.0f / fmaxf(sqrtf(ss), 1e-12f);
    uint8_t* dst = outb + (size_t)row*CDIM;
    #pragma unroll
    for (int w=0; w<4; w++){
        uint32_t lo = f2_e4m3x2(v[w].y*inv, v[w].x*inv);   // bytes [x,y]
        uint32_t hi = f2_e4m3x2(v[w].w*inv, v[w].z*inv);   // bytes [z,w]
        *(uint32_t*)(dst + (lane + w*32)*4) = lo | (hi << 16);
    }
    if (MODE && lane==0) g_minv[row] = inv;
}

// ---------------------------------------------------------------------------
// Kernel 3: e4m3 mma.sync GEMM (128q x 128m tiles, K=512 resident Q) with
// threshold-filtered streaming top-5.
//   - per-row 5th-best threshold in SMEM; after each tile every thread
//     filters its 32 fp32 fragment values against it (record statistics:
//     ~1 pass/row/tile) and pushes passers into per-row SMEM buckets.
//   - 128 owner threads drain buckets; full fp32 spill+scan only for tile 0
//     and bucket-overflow tiles (correctness fallback).
// ---------------------------------------------------------------------------
__global__ void __launch_bounds__(256,1) sim_topk_fp8(){
    extern __shared__ __align__(16) char sm[];
    uint8_t* sQ      = (uint8_t*)sm;
    float*   sSim    = (float*)(sm + SS_OFF);
    float*   sThresh = (float*)(sm + TH_OFF);
    int*     sCnt    = (int*)(sm + CNT_OFF);
    float*   sBS     = (float*)(sm + BS_OFF);
    int*     sBC     = (int*)(sm + BC_OFF);
    int*     sOver   = (int*)(sm + OVR_OFF);

    const int tid  = threadIdx.x;
    const int lane = tid & 31;
    const int wid  = tid >> 5;
    const int chunk = blockIdx.x;
    const int qbase = blockIdx.y * QT;
    const int mbase = chunk * MCHUNK;

    if (tid == 0) sOver[0] = 0;

    // ---- Load resident Q tile (128 x 512 fp8, padded rows) ----
    {
        const uint4* gq = (const uint4*)g_qn8;   // 32 uint4 per row
        #pragma unroll
        for (int i=0; i<(QT*32)/256; i++){
            int idx = tid + i*256;
            int r = idx >> 5, c = idx & 31;
            uint4 v = gq[(size_t)(qbase + r)*32 + c];
            *(uint4*)(sQ + r*SQ_STRIDE + c*16) = v;
        }
    }

    // ---- producer: each thread copies 4x16B per 128x128 fp8 chunk ----
    const int rowt = tid >> 3;          // 0..31 (rows rowt + 32i)
    const int c16  = tid & 7;           // 16B column (8 per row)
    const uint8_t* gmb = g_mn8;

    auto issue_chunk = [&](int cidx, int stage){
        int mt = cidx >> 2, kc = cidx & 3;
        const uint8_t* src = gmb
            + (size_t)(mbase + mt*NT + rowt)*CDIM + kc*KC + c16*16;
        uint32_t dst = smem_u32(sm + SM_OFF + stage*CHUNK_BYTES
                                + rowt*SM_STRIDE + c16*16);
        #pragma unroll
        for (int i=0; i<4; i++)
            cp_async16(dst + i*32*SM_STRIDE, src + (size_t)i*32*CDIM);
    };

    issue_chunk(0, 0); cp_commit();
    issue_chunk(1, 1); cp_commit();

    const int wq = (wid & 1) * 64;      // warp's 64-query slab
    const int wn = (wid >> 1) * 32;     // warp's 32-memory-col slab

    // owner-thread running top-5 (threads < 128; thread r owns query row r)
    float s0=-2.f,s1=-2.f,s2=-2.f,s3=-2.f,s4=-2.f;
    int   i0=0,i1=0,i2=0,i3=0,i4=0;

    int s_cons = 0, s_prod = 2;         // ring cursors (mod 3)

    for (int mt=0; mt<MT_PER; mt++){
        float acc[4][4][4];
        #pragma unroll
        for (int a=0;a<4;a++)
            #pragma unroll
            for (int b=0;b<4;b++)
                #pragma unroll
                for (int d=0;d<4;d++) acc[a][b][d]=0.f;

        #pragma unroll 1
        for (int kc=0; kc<NKC; kc++){
            const int cidx = mt*NKC + kc;
            cp_wait<1>();
            __syncthreads();
            if (cidx + 2 < NCHUNKS) issue_chunk(cidx + 2, s_prod);
            cp_commit();
            if (++s_prod == NSTAGE) s_prod = 0;

            const uint8_t* mb = (const uint8_t*)(sm + SM_OFF + s_cons*CHUNK_BYTES);
            if (++s_cons == NSTAGE) s_cons = 0;

            #pragma unroll
            for (int k32=0; k32<KC/32; k32++){
                uint32_t bfr[4][2];
                #pragma unroll
                for (int ntp=0; ntp<2; ntp++){
                    int brow = wn + ntp*16 + ((lane>>4)&1)*8 + (lane&7);
                    int bkB  = k32*32 + ((lane>>3)&1)*16;
                    uint32_t ba = smem_u32(mb + brow*SM_STRIDE + bkB);
                    asm volatile("ldmatrix.sync.aligned.m8n8.x4.shared.b16 {%0,%1,%2,%3}, [%4];"
                                 : "=r"(bfr[ntp*2][0]),   "=r"(bfr[ntp*2][1]),
                                   "=r"(bfr[ntp*2+1][0]), "=r"(bfr[ntp*2+1][1]) : "r"(ba));
                }
                #pragma unroll
                for (int qt=0; qt<4; qt++){
                    uint32_t a0,a1,a2,a3;
                    int arow = wq + qt*16 + (lane & 15);
                    int akB  = kc*KC + k32*32 + (lane >> 4)*16;
                    uint32_t aa = smem_u32(sQ + arow*SQ_STRIDE + akB);
                    asm volatile("ldmatrix.sync.aligned.m8n8.x4.shared.b16 {%0,%1,%2,%3}, [%4];"
                                 : "=r"(a0),"=r"(a1),"=r"(a2),"=r"(a3) : "r"(aa));
                    #pragma unroll
                    for (int nt=0; nt<4; nt++){
                        asm volatile(
                          "mma.sync.aligned.m16n8k32.row.col.f32.e4m3.e4m3.f32 "
                          "{%0,%1,%2,%3}, {%4,%5,%6,%7}, {%8,%9}, {%0,%1,%2,%3};"
                          : "+f"(acc[qt][nt][0]),"+f"(acc[qt][nt][1]),
                            "+f"(acc[qt][nt][2]),"+f"(acc[qt][nt][3])
                          : "r"(a0),"r"(a1),"r"(a2),"r"(a3),
                            "r"(bfr[nt][0]),"r"(bfr[nt][1]));
                    }
                }
            }
        }

        const int mrow0 = mbase + mt*NT;
        bool dospill;

        if (mt == 0){
            dospill = true;
        } else {
            // ---- threshold filter: push record-beating values to buckets ----
            #pragma unroll
            for (int qt=0; qt<4; qt++){
                #pragma unroll
                for (int rp=0; rp<2; rp++){
                    int r = wq + qt*16 + (lane>>2) + rp*8;
                    float th = sThresh[r];
                    #pragma unroll
                    for (int nt=0; nt<4; nt++){
                        float v0 = acc[qt][nt][rp*2+0];
                        float v1 = acc[qt][nt][rp*2+1];
                        int c = wn + nt*8 + (lane&3)*2;
                        if (v0 > th){
                            int s = atomicAdd(&sCnt[r], 1);
                            if (s < CAP){ sBS[r*CAP+s]=v0; sBC[r*CAP+s]=c; }
                            else sOver[0] = 1;
                        }
                        if (v1 > th){
                            int s = atomicAdd(&sCnt[r], 1);
                            if (s < CAP){ sBS[r*CAP+s]=v1; sBC[r*CAP+s]=c+1; }
                            else sOver[0] = 1;
                        }
                    }
                }
            }
            __syncthreads();
            dospill = (sOver[0] != 0);
        }

        if (dospill){
            // ---- fp32 spill (rare: tile 0 + overflow tiles) ----
            #pragma unroll
            for (int qt=0; qt<4; qt++){
                #pragma unroll
                for (int nt=0; nt<4; nt++){
                    int r = wq + qt*16 + (lane >> 2);
                    int c = wn + nt*8  + (lane & 3)*2;
                    *(float2*)(sSim + r*SS_STRIDEF + c) =
                        make_float2(acc[qt][nt][0], acc[qt][nt][1]);
                    *(float2*)(sSim + (r+8)*SS_STRIDEF + c) =
                        make_float2(acc[qt][nt][2], acc[qt][nt][3]);
                }
            }
            __syncthreads();
        }

        if (tid < QT){
            const int r = tid;
            const int n = (mt == 0) ? (CAP+1) : sCnt[r];
            if (n > CAP){
                // fallback: exact full-row scan from spill
                const float* row = sSim + r*SS_STRIDEF;
                #pragma unroll 4
                for (int c=0; c<NT; c++){
                    float v = row[c];
                    TOP5_INSERT(v, mrow0 + c);
                }
            } else {
                for (int s=0; s<n; s++){
                    float v = sBS[r*CAP+s];
                    TOP5_INSERT(v, mrow0 + sBC[r*CAP+s]);
                }
            }
            sThresh[r] = s4;
            sCnt[r] = 0;
        }
        if (dospill && tid == 0) sOver[0] = 0;
        // next tile's mainloop __syncthreads orders these writes vs. reuse
    }

    if (tid < QT){
        int q = qbase + tid;
        int* ci = g_cidx + (size_t)q*NCAND + chunk*TOPK;
        ci[0]=i0; ci[1]=i1; ci[2]=i2; ci[3]=i3; ci[4]=i4;
    }
}

// ---------------------------------------------------------------------------
// Kernel 4: exact fp32 rescore of 40 candidates, true top-5, softmax, gather,
// out = x + 0.5 * retrieved. One warp per query.
// ---------------------------------------------------------------------------
__global__ void merge_kernel(const float* __restrict__ x,
                             const float* __restrict__ mem,
                             float* __restrict__ out){
    int gw   = (blockIdx.x*blockDim.x + threadIdx.x) >> 5;
    int lane = threadIdx.x & 31;
    if (gw >= NQ) return;

    const float4* xr = (const float4*)(x + (size_t)gw*CDIM);
    float4 xv[4];
    float ss = 0.f;
    #pragma unroll
    for (int w=0; w<4; w++){
        xv[w] = xr[lane + w*32];
        ss += xv[w].x*xv[w].x + xv[w].y*xv[w].y + xv[w].z*xv[w].z + xv[w].w*xv[w].w;
    }
    ss = warp_sum(ss);
    float qinv = 1.0f / fmaxf(sqrtf(ss), 1e-12f);

    float ts[TOPK]; int ti[TOPK];
    #pragma unroll
    for (int r=0;r<TOPK;r++){ ts[r]=-2.f; ti[r]=0; }

    for (int c=0; c<NCAND; c++){
        int idx = g_cidx[(size_t)gw*NCAND + c];
        const float4* mr = (const float4*)(mem + (size_t)idx*CDIM);
        float d = 0.f;
        #pragma unroll
        for (int w=0; w<4; w++){
            float4 mv = mr[lane + w*32];
            d += xv[w].x*mv.x + xv[w].y*mv.y + xv[w].z*mv.z + xv[w].w*mv.w;
        }
        d = warp_sum(d);
        float sc = d * qinv * g_minv[idx];
        if (sc > ts[TOPK-1]){
            ts[TOPK-1]=sc; ti[TOPK-1]=idx;
            #pragma unroll
            for (int r=TOPK-1; r>0; r--){
                if (ts[r] > ts[r-1]){
                    float t=ts[r]; ts[r]=ts[r-1]; ts[r-1]=t;
                    int   u=ti[r]; ti[r]=ti[r-1]; ti[r-1]=u;
                }
            }
        }
    }

    float wv[TOPK], sum=0.f;
    #pragma unroll
    for (int r=0;r<TOPK;r++){ wv[r] = expf(ts[r]-ts[0]); sum += wv[r]; }
    float isum = 1.0f/sum;

    float4 o[4];
    #pragma unroll
    for (int w4=0; w4<4; w4++) o[w4] = xv[w4];
    #pragma unroll
    for (int r=0; r<TOPK; r++){
        float wr = 0.5f * wv[r] * isum;
        const float4* mr = (const float4*)(mem + (size_t)ti[r]*CDIM);
        #pragma unroll
        for (int w4=0; w4<4; w4++){
            float4 mv = mr[lane + w4*32];
            o[w4].x += wr*mv.x; o[w4].y += wr*mv.y;
            o[w4].z += wr*mv.z; o[w4].w += wr*mv.w;
        }
    }
    float4* orow = (float4*)(out + (size_t)gw*CDIM);
    #pragma unroll
    for (int w4=0; w4<4; w4++) orow[lane + w4*32] = o[w4];
}

// ---------------------------------------------------------------------------
extern "C" void kernel_launch(void* const* d_in, const int* in_sizes, int n_in,
                              void* d_out, int out_size){
    const float* x   = (const float*)d_in[0];   // [4,2048,512]
    const float* mem = (const float*)d_in[1];   // [32768,512]
    float* out = (float*)d_out;

    cudaFuncSetAttribute(sim_topk_fp8,
                         cudaFuncAttributeMaxDynamicSharedMemorySize, SMEM_BYTES);

    normalize_kernel<0><<<NQ/8, 256>>>(x);
    normalize_kernel<1><<<MROWS/8, 256>>>(mem);
    sim_topk_fp8<<<dim3(NCH, NQ/QT), 256, SMEM_BYTES>>>();
    merge_kernel<<<(NQ*32)/256, 256>>>(x, mem, out);
}

// round 8
// speedup vs baseline: 1.5003x; 1.0799x over previous
#include <cuda_runtime.h>
#include <cuda_bf16.h>
#include <cstdint>

// Problem constants
#define NQ      8192
#define CDIM    512
#define MROWS   32768
#define TOPK    5
#define NCH     8
#define MCHUNK  (MROWS/NCH)   // 4096
#define NCAND   (NCH*TOPK)    // 40

// GEMM tiling (family-common ISA: fp8 mma.sync m16n8k32 + ldmatrix + cp.async)
#define THREADS   512
#define QT        128         // queries per block
#define NT        128         // memory rows per tile
#define MT_PER    (MCHUNK/NT) // 32 tiles per block
#define KC        128         // k elements (fp8) per staged chunk
#define NKC       (CDIM/KC)   // 4
#define NCHUNKS   (MT_PER*NKC)// 128
#define NSTAGE    3
#define CAP       12          // per-row bucket capacity per tile

#define SQ_STRIDE 528                          // bytes per sQ row (512 + 16 pad)
#define SM_STRIDE 144                          // bytes per sM row (128 + 16 pad)
#define SS_STRIDEF 130                         // floats per sSim row (128 + 2)

#define SQ_BYTES    (QT*SQ_STRIDE)             // 67584
#define CHUNK_BYTES (NT*SM_STRIDE)             // 18432
#define SM_OFF      SQ_BYTES
#define SS_OFF      (SM_OFF + NSTAGE*CHUNK_BYTES)   // 122880
#define TH_OFF      (SS_OFF + QT*SS_STRIDEF*4)      // 189440
#define CNT_OFF     (TH_OFF + 512)                  // 189952
#define BS_OFF      (CNT_OFF + 512)                 // 190464
#define BC_OFF      (BS_OFF + QT*CAP*4)             // 196608
#define OVR_OFF     (BC_OFF + QT*CAP*4)             // 202752
#define SMEM_BYTES  (OVR_OFF + 16)

// Scratch (device globals: allocation-free)
__device__ __align__(256) uint8_t g_qn8[(size_t)NQ*CDIM];     // e4m3 normalized queries
__device__ __align__(256) uint8_t g_mn8[(size_t)MROWS*CDIM];  // e4m3 normalized memory
__device__ float g_minv[MROWS];
__device__ int   g_cidx[(size_t)NQ*NCAND];

__device__ __forceinline__ uint32_t smem_u32(const void* p){
    return (uint32_t)__cvta_generic_to_shared(p);
}
__device__ __forceinline__ float warp_sum(float v){
    #pragma unroll
    for (int o=16;o;o>>=1) v += __shfl_xor_sync(0xffffffffu, v, o);
    return v;
}
__device__ __forceinline__ void cp_async16(uint32_t dst, const void* src){
    asm volatile("cp.async.cg.shared.global [%0], [%1], 16;"
                 :: "r"(dst), "l"(src) : "memory");
}
__device__ __forceinline__ void cp_commit(){
    asm volatile("cp.async.commit_group;" ::: "memory");
}
template<int N>
__device__ __forceinline__ void cp_wait(){
    asm volatile("cp.async.wait_group %0;" :: "n"(N) : "memory");
}
// pack 2 floats -> e4m3x2 (a -> upper byte, b -> lower byte)
__device__ __forceinline__ uint16_t f2_e4m3x2(float a, float b){
    uint16_t r;
    asm("cvt.rn.satfinite.e4m3x2.f32 %0, %1, %2;" : "=h"(r) : "f"(a), "f"(b));
    return r;
}

// top-5 insert (strict >, earlier index wins ties)
#define TOP5_INSERT(v, id) do { \
    if ((v) > s4){ \
        if ((v) > s2){ \
            if ((v) > s1){ \
                if ((v) > s0){ s4=s3;i4=i3; s3=s2;i3=i2; s2=s1;i2=i1; s1=s0;i1=i0; s0=(v);i0=(id); } \
                else         { s4=s3;i4=i3; s3=s2;i3=i2; s2=s1;i2=i1; s1=(v);i1=(id); } \
            } else           { s4=s3;i4=i3; s3=s2;i3=i2; s2=(v);i2=(id); } \
        } else { \
            if ((v) > s3)    { s4=s3;i4=i3; s3=(v);i3=(id); } \
            else             { s4=(v);i4=(id); } \
        } \
    } \
} while(0)

// ---------------------------------------------------------------------------
// Kernel 1/2: L2-normalize rows (fp32 in -> e4m3 out). MODE 0: queries, 1: memory.
// ---------------------------------------------------------------------------
template<int MODE>
__global__ void normalize_kernel(const float* __restrict__ in){
    const int rows = MODE ? MROWS : NQ;
    uint8_t* outb = MODE ? g_mn8 : g_qn8;
    int row  = blockIdx.x*8 + (threadIdx.x >> 5);
    int lane = threadIdx.x & 31;
    if (row >= rows) return;
    const float4* src = (const float4*)(in + (size_t)row*CDIM);
    float4 v[4];
    float ss = 0.f;
    #pragma unroll
    for (int w=0; w<4; w++){
        v[w] = src[lane + w*32];
        ss += v[w].x*v[w].x + v[w].y*v[w].y + v[w].z*v[w].z + v[w].w*v[w].w;
    }
    ss = warp_sum(ss);
    float inv = 1.0f / fmaxf(sqrtf(ss), 1e-12f);
    uint8_t* dst = outb + (size_t)row*CDIM;
    #pragma unroll
    for (int w=0; w<4; w++){
        uint32_t lo = f2_e4m3x2(v[w].y*inv, v[w].x*inv);   // bytes [x,y]
        uint32_t hi = f2_e4m3x2(v[w].w*inv, v[w].z*inv);   // bytes [z,w]
        *(uint32_t*)(dst + (lane + w*32)*4) = lo | (hi << 16);
    }
    if (MODE && lane==0) g_minv[row] = inv;
}

// ---------------------------------------------------------------------------
// Kernel 3: e4m3 mma.sync GEMM, 512 threads (4 warps/SMSP issue experiment).
// 16 warps, warp tile = 32q x 32n (acc 2x4x4). Threshold-filtered top-5.
// ---------------------------------------------------------------------------
__global__ void __launch_bounds__(THREADS,1) sim_topk_fp8(){
    extern __shared__ __align__(16) char sm[];
    uint8_t* sQ      = (uint8_t*)sm;
    float*   sSim    = (float*)(sm + SS_OFF);
    float*   sThresh = (float*)(sm + TH_OFF);
    int*     sCnt    = (int*)(sm + CNT_OFF);
    float*   sBS     = (float*)(sm + BS_OFF);
    int*     sBC     = (int*)(sm + BC_OFF);
    int*     sOver   = (int*)(sm + OVR_OFF);

    const int tid  = threadIdx.x;
    const int lane = tid & 31;
    const int wid  = tid >> 5;
    const int chunk = blockIdx.x;
    const int qbase = blockIdx.y * QT;
    const int mbase = chunk * MCHUNK;

    if (tid == 0) sOver[0] = 0;

    // ---- Load resident Q tile (128 x 512 fp8, padded rows) ----
    {
        const uint4* gq = (const uint4*)g_qn8;   // 32 uint4 per row
        #pragma unroll
        for (int i=0; i<(QT*32)/THREADS; i++){
            int idx = tid + i*THREADS;
            int r = idx >> 5, c = idx & 31;
            uint4 v = gq[(size_t)(qbase + r)*32 + c];
            *(uint4*)(sQ + r*SQ_STRIDE + c*16) = v;
        }
    }

    // ---- producer: each thread copies 2x16B per 128x128 fp8 chunk ----
    const int rowt = tid >> 3;          // 0..63 (rows rowt, rowt+64)
    const int c16  = tid & 7;           // 16B column (8 per row)
    const uint8_t* gmb = g_mn8;

    auto issue_chunk = [&](int cidx, int stage){
        int mt = cidx >> 2, kc = cidx & 3;
        const uint8_t* src = gmb
            + (size_t)(mbase + mt*NT + rowt)*CDIM + kc*KC + c16*16;
        uint32_t dst = smem_u32(sm + SM_OFF + stage*CHUNK_BYTES
                                + rowt*SM_STRIDE + c16*16);
        #pragma unroll
        for (int i=0; i<2; i++)
            cp_async16(dst + i*64*SM_STRIDE, src + (size_t)i*64*CDIM);
    };

    issue_chunk(0, 0); cp_commit();
    issue_chunk(1, 1); cp_commit();

    const int wq = (wid & 3) * 32;      // warp's 32-query slab
    const int wn = (wid >> 2) * 32;     // warp's 32-memory-col slab

    // owner-thread running top-5 (threads < 128; thread r owns query row r)
    float s0=-2.f,s1=-2.f,s2=-2.f,s3=-2.f,s4=-2.f;
    int   i0=0,i1=0,i2=0,i3=0,i4=0;

    int s_cons = 0, s_prod = 2;         // ring cursors (mod 3)

    for (int mt=0; mt<MT_PER; mt++){
        float acc[2][4][4];
        #pragma unroll
        for (int a=0;a<2;a++)
            #pragma unroll
            for (int b=0;b<4;b++)
                #pragma unroll
                for (int d=0;d<4;d++) acc[a][b][d]=0.f;

        #pragma unroll 1
        for (int kc=0; kc<NKC; kc++){
            const int cidx = mt*NKC + kc;
            cp_wait<1>();
            __syncthreads();
            if (cidx + 2 < NCHUNKS) issue_chunk(cidx + 2, s_prod);
            cp_commit();
            if (++s_prod == NSTAGE) s_prod = 0;

            const uint8_t* mb = (const uint8_t*)(sm + SM_OFF + s_cons*CHUNK_BYTES);
            if (++s_cons == NSTAGE) s_cons = 0;

            #pragma unroll
            for (int k32=0; k32<KC/32; k32++){
                uint32_t bfr[4][2];
                #pragma unroll
                for (int ntp=0; ntp<2; ntp++){
                    int brow = wn + ntp*16 + ((lane>>4)&1)*8 + (lane&7);
                    int bkB  = k32*32 + ((lane>>3)&1)*16;
                    uint32_t ba = smem_u32(mb + brow*SM_STRIDE + bkB);
                    asm volatile("ldmatrix.sync.aligned.m8n8.x4.shared.b16 {%0,%1,%2,%3}, [%4];"
                                 : "=r"(bfr[ntp*2][0]),   "=r"(bfr[ntp*2][1]),
                                   "=r"(bfr[ntp*2+1][0]), "=r"(bfr[ntp*2+1][1]) : "r"(ba));
                }
                #pragma unroll
                for (int qt=0; qt<2; qt++){
                    uint32_t a0,a1,a2,a3;
                    int arow = wq + qt*16 + (lane & 15);
                    int akB  = kc*KC + k32*32 + (lane >> 4)*16;
                    uint32_t aa = smem_u32(sQ + arow*SQ_STRIDE + akB);
                    asm volatile("ldmatrix.sync.aligned.m8n8.x4.shared.b16 {%0,%1,%2,%3}, [%4];"
                                 : "=r"(a0),"=r"(a1),"=r"(a2),"=r"(a3) : "r"(aa));
                    #pragma unroll
                    for (int nt=0; nt<4; nt++){
                        asm volatile(
                          "mma.sync.aligned.m16n8k32.row.col.f32.e4m3.e4m3.f32 "
                          "{%0,%1,%2,%3}, {%4,%5,%6,%7}, {%8,%9}, {%0,%1,%2,%3};"
                          : "+f"(acc[qt][nt][0]),"+f"(acc[qt][nt][1]),
                            "+f"(acc[qt][nt][2]),"+f"(acc[qt][nt][3])
                          : "r"(a0),"r"(a1),"r"(a2),"r"(a3),
                            "r"(bfr[nt][0]),"r"(bfr[nt][1]));
                    }
                }
            }
        }

        const int mrow0 = mbase + mt*NT;
        bool dospill;

        if (mt == 0){
            dospill = true;
        } else {
            // ---- threshold filter: push record-beating values to buckets ----
            #pragma unroll
            for (int qt=0; qt<2; qt++){
                #pragma unroll
                for (int rp=0; rp<2; rp++){
                    int r = wq + qt*16 + (lane>>2) + rp*8;
                    float th = sThresh[r];
                    #pragma unroll
                    for (int nt=0; nt<4; nt++){
                        float v0 = acc[qt][nt][rp*2+0];
                        float v1 = acc[qt][nt][rp*2+1];
                        int c = wn + nt*8 + (lane&3)*2;
                        if (v0 > th){
                            int s = atomicAdd(&sCnt[r], 1);
                            if (s < CAP){ sBS[r*CAP+s]=v0; sBC[r*CAP+s]=c; }
                            else sOver[0] = 1;
                        }
                        if (v1 > th){
                            int s = atomicAdd(&sCnt[r], 1);
                            if (s < CAP){ sBS[r*CAP+s]=v1; sBC[r*CAP+s]=c+1; }
                            else sOver[0] = 1;
                        }
                    }
                }
            }
            __syncthreads();
            dospill = (sOver[0] != 0);
        }

        if (dospill){
            // ---- fp32 spill (rare: tile 0 + overflow tiles) ----
            #pragma unroll
            for (int qt=0; qt<2; qt++){
                #pragma unroll
                for (int nt=0; nt<4; nt++){
                    int r = wq + qt*16 + (lane >> 2);
                    int c = wn + nt*8  + (lane & 3)*2;
                    *(float2*)(sSim + r*SS_STRIDEF + c) =
                        make_float2(acc[qt][nt][0], acc[qt][nt][1]);
                    *(float2*)(sSim + (r+8)*SS_STRIDEF + c) =
                        make_float2(acc[qt][nt][2], acc[qt][nt][3]);
                }
            }
            __syncthreads();
        }

        if (tid < QT){
            const int r = tid;
            const int n = (mt == 0) ? (CAP+1) : sCnt[r];
            if (n > CAP){
                // fallback: exact full-row scan from spill
                const float* row = sSim + r*SS_STRIDEF;
                #pragma unroll 4
                for (int c=0; c<NT; c++){
                    float v = row[c];
                    TOP5_INSERT(v, mrow0 + c);
                }
            } else {
                for (int s=0; s<n; s++){
                    float v = sBS[r*CAP+s];
                    TOP5_INSERT(v, mrow0 + sBC[r*CAP+s]);
                }
            }
            sThresh[r] = s4;
            sCnt[r] = 0;
        }
        if (dospill && tid == 0) sOver[0] = 0;
        // next tile's mainloop __syncthreads orders these writes vs. reuse
    }

    if (tid < QT){
        int q = qbase + tid;
        int* ci = g_cidx + (size_t)q*NCAND + chunk*TOPK;
        ci[0]=i0; ci[1]=i1; ci[2]=i2; ci[3]=i3; ci[4]=i4;
    }
}

// ---------------------------------------------------------------------------
// Kernel 4: exact fp32 rescore of 40 candidates, true top-5, softmax, gather,
// out = x + 0.5 * retrieved. One warp per query.
// ---------------------------------------------------------------------------
__global__ void merge_kernel(const float* __restrict__ x,
                             const float* __restrict__ mem,
                             float* __restrict__ out){
    int gw   = (blockIdx.x*blockDim.x + threadIdx.x) >> 5;
    int lane = threadIdx.x & 31;
    if (gw >= NQ) return;

    const float4* xr = (const float4*)(x + (size_t)gw*CDIM);
    float4 xv[4];
    float ss = 0.f;
    #pragma unroll
    for (int w=0; w<4; w++){
        xv[w] = xr[lane + w*32];
        ss += xv[w].x*xv[w].x + xv[w].y*xv[w].y + xv[w].z*xv[w].z + xv[w].w*xv[w].w;
    }
    ss = warp_sum(ss);
    float qinv = 1.0f / fmaxf(sqrtf(ss), 1e-12f);

    float ts[TOPK]; int ti[TOPK];
    #pragma unroll
    for (int r=0;r<TOPK;r++){ ts[r]=-2.f; ti[r]=0; }

    for (int c=0; c<NCAND; c++){
        int idx = g_cidx[(size_t)gw*NCAND + c];
        const float4* mr = (const float4*)(mem + (size_t)idx*CDIM);
        float d = 0.f;
        #pragma unroll
        for (int w=0; w<4; w++){
            float4 mv = mr[lane + w*32];
            d += xv[w].x*mv.x + xv[w].y*mv.y + xv[w].z*mv.z + xv[w].w*mv.w;
        }
        d = warp_sum(d);
        float sc = d * qinv * g_minv[idx];
        if (sc > ts[TOPK-1]){
            ts[TOPK-1]=sc; ti[TOPK-1]=idx;
            #pragma unroll
            for (int r=TOPK-1; r>0; r--){
                if (ts[r] > ts[r-1]){
                    float t=ts[r]; ts[r]=ts[r-1]; ts[r-1]=t;
                    int   u=ti[r]; ti[r]=ti[r-1]; ti[r-1]=u;
                }
            }
        }
    }

    float wv[TOPK], sum=0.f;
    #pragma unroll
    for (int r=0;r<TOPK;r++){ wv[r] = expf(ts[r]-ts[0]); sum += wv[r]; }
    float isum = 1.0f/sum;

    float4 o[4];
    #pragma unroll
    for (int w4=0; w4<4; w4++) o[w4] = xv[w4];
    #pragma unroll
    for (int r=0; r<TOPK; r++){
        float wr = 0.5f * wv[r] * isum;
        const float4* mr = (const float4*)(mem + (size_t)ti[r]*CDIM);
        #pragma unroll
        for (int w4=0; w4<4; w4++){
            float4 mv = mr[lane + w4*32];
            o[w4].x += wr*mv.x; o[w4].y += wr*mv.y;
            o[w4].z += wr*mv.z; o[w4].w += wr*mv.w;
        }
    }
    float4* orow = (float4*)(out + (size_t)gw*CDIM);
    #pragma unroll
    for (int w4=0; w4<4; w4++) orow[lane + w4*32] = o[w4];
}

// ---------------------------------------------------------------------------
extern "C" void kernel_launch(void* const* d_in, const int* in_sizes, int n_in,
                              void* d_out, int out_size){
    const float* x   = (const float*)d_in[0];   // [4,2048,512]
    const float* mem = (const float*)d_in[1];   // [32768,512]
    float* out = (float*)d_out;

    cudaFuncSetAttribute(sim_topk_fp8,
                         cudaFuncAttributeMaxDynamicSharedMemorySize, SMEM_BYTES);

    normalize_kernel<0><<<NQ/8, 256>>>(x);
    normalize_kernel<1><<<MROWS/8, 256>>>(mem);
    sim_topk_fp8<<<dim3(NCH, NQ/QT), THREADS, SMEM_BYTES>>>();
    merge_kernel<<<(NQ*32)/256, 256>>>(x, mem, out);
}